// round 1
// baseline (speedup 1.0000x reference)
#include <cuda_runtime.h>
#include <cstdint>
#include <cstddef>

#define NN 10000
#define EE 160000
#define BB 2
#define FIN 32
#define TT 16
#define CC 64
#define PAIRS (BB*NN)          // 20000
#define NODE_FLOATS (FIN*TT)   // 512 per (b,n)

// ---------------- device scratch (no allocs allowed) ----------------
__device__ float d_Tx1[(size_t)PAIRS * NODE_FLOATS];  // L x
__device__ float d_P2 [(size_t)PAIRS * NODE_FLOATS];  // L (L x)
__device__ int   d_degc[NN];
__device__ float d_dinv[NN];
__device__ int   d_cnt[NN];
__device__ int   d_ptr[NN + 1];
__device__ int   d_wr[NN];
__device__ int   d_csrc[EE];
__device__ float d_csw[EE];

// ---------------- CSR build ----------------
__global__ void zero_counts_kernel() {
    int i = blockIdx.x * blockDim.x + threadIdx.x;
    if (i < NN) { d_degc[i] = 0; d_cnt[i] = 0; }
}

__global__ void count_kernel(const int* __restrict__ row, const int* __restrict__ col) {
    int e = blockIdx.x * blockDim.x + threadIdx.x;
    if (e < EE) {
        atomicAdd(&d_degc[row[e]], 1);
        atomicAdd(&d_cnt[col[e]], 1);
    }
}

__global__ void dinv_kernel() {
    int i = blockIdx.x * blockDim.x + threadIdx.x;
    if (i < NN) {
        int d = d_degc[i];
        d_dinv[i] = (d > 0) ? rsqrtf((float)d) : 0.f;
    }
}

__global__ void scan_kernel() {
    __shared__ int sh[1024];
    __shared__ int carry;
    int tid = threadIdx.x;
    if (tid == 0) carry = 0;
    __syncthreads();
    for (int base = 0; base < NN; base += 1024) {
        int i = base + tid;
        int v = (i < NN) ? d_cnt[i] : 0;
        sh[tid] = v;
        __syncthreads();
        for (int off = 1; off < 1024; off <<= 1) {
            int t = (tid >= off) ? sh[tid - off] : 0;
            __syncthreads();
            sh[tid] += t;
            __syncthreads();
        }
        int incl = sh[tid];
        int c0 = carry;
        if (i < NN) { int ex = c0 + incl - v; d_ptr[i] = ex; d_wr[i] = ex; }
        int tot = sh[1023];
        __syncthreads();
        if (tid == 0) carry = c0 + tot;
        __syncthreads();
    }
    if (tid == 0) d_ptr[NN] = carry;
}

__global__ void fill_kernel(const int* __restrict__ row, const int* __restrict__ col) {
    int e = blockIdx.x * blockDim.x + threadIdx.x;
    if (e < EE) {
        int r = row[e], c = col[e];
        float wv = -(d_dinv[r] * d_dinv[c]);
        int pos = atomicAdd(&d_wr[c], 1);
        d_csrc[pos] = r;
        d_csw[pos]  = wv;
    }
}

// ---------------- propagation: out[n] = sum_{e: col=n} w_e * z[src_e] ----------------
// grid: NN blocks of 256 threads. Each thread owns one float4 of the 1024-float
// (B,F,T) node payload; edge gather is coalesced 2KB-contiguous per source node.
__global__ __launch_bounds__(256) void prop_kernel(const float* __restrict__ z,
                                                   float* __restrict__ outp) {
    int n = blockIdx.x;
    int tid = threadIdx.x;
    int b = tid >> 7;        // 0..1
    int q = tid & 127;       // float4 index within (F,T)=512 floats
    const float4* zb = reinterpret_cast<const float4*>(z) + (size_t)b * NN * 128;
    float4 acc = make_float4(0.f, 0.f, 0.f, 0.f);
    int s = d_ptr[n], e = d_ptr[n + 1];
    int k = s;
    for (; k + 1 < e; k += 2) {
        int u0 = d_csrc[k], u1 = d_csrc[k + 1];
        float w0 = d_csw[k], w1 = d_csw[k + 1];
        float4 v0 = zb[(size_t)u0 * 128 + q];
        float4 v1 = zb[(size_t)u1 * 128 + q];
        acc.x += w0 * v0.x + w1 * v1.x;
        acc.y += w0 * v0.y + w1 * v1.y;
        acc.z += w0 * v0.z + w1 * v1.z;
        acc.w += w0 * v0.w + w1 * v1.w;
    }
    if (k < e) {
        int u0 = d_csrc[k];
        float w0 = d_csw[k];
        float4 v0 = zb[(size_t)u0 * 128 + q];
        acc.x += w0 * v0.x; acc.y += w0 * v0.y;
        acc.z += w0 * v0.z; acc.w += w0 * v0.w;
    }
    reinterpret_cast<float4*>(outp)[(size_t)b * NN * 128 + (size_t)n * 128 + q] = acc;
}

// ---------------- fused dense kernel ----------------
// Per (b,n): s = relu([x;Lx;2LLx-x... folded] @ W + b)   (cheb, 64x16)
//            res = x @ resW                              (64x16)
//            tc  = temporal conv3 over s                 (64x16)
//            z = relu(res+tc+bias); LayerNorm over channels; out (64,16)
// Block = 256 threads = 4 pairs x 64 threads; 4 iterations -> 16 pairs/block.
// Smem: A1T[128][64] (cheb rows 0..95 + res rows 96..127, k-major),
//       A2T[192][64] (time weights, (c*3+dt)-major, o contiguous),
//       biases, 4x 1536-float pair regions (B1 input tile aliased with padded s tile).

#define SM_A1T   0
#define SM_A2T   8192
#define SM_BIAS  20480
#define SM_PAIR  20736
#define SM_FLOATS 26880
#define SMEM_BYTES (SM_FLOATS * 4)
#define ITERS 4
#define FUSED_GRID 1250   // 1250 * 4 * 4 = 20000 pairs

__global__ __launch_bounds__(256, 2) void fused_kernel(
    const float* __restrict__ x,
    const float* __restrict__ cheb_W,   // (3,32,64)
    const float* __restrict__ cheb_b,   // (64)
    const float* __restrict__ time_W,   // (64,64,1,3)
    const float* __restrict__ time_b,   // (64)
    const float* __restrict__ res_W,    // (64,32)
    const float* __restrict__ res_b,    // (64)
    const float* __restrict__ ln_g,     // (64)
    const float* __restrict__ ln_b,     // (64)
    float* __restrict__ out)            // (B,N,64,16)
{
    extern __shared__ float smf[];
    float* A1T  = smf + SM_A1T;    // [128][64]
    float* A2T  = smf + SM_A2T;    // [192][64]
    float* BIAS = smf + SM_BIAS;   // chb[64] zb[64] lng[64] lnb[64]
    float* PAIR = smf + SM_PAIR;   // 4 * 1536

    int tid = threadIdx.x;

    // ---- load & transform weights into smem (once per block) ----
    for (int i = tid; i < 2048; i += 256) A1T[i]        = cheb_W[i] - cheb_W[4096 + i]; // W0 - W2
    for (int i = tid; i < 2048; i += 256) A1T[2048 + i] = cheb_W[2048 + i];             // W1
    for (int i = tid; i < 2048; i += 256) A1T[4096 + i] = 2.f * cheb_W[4096 + i];       // 2*W2
    for (int i = tid; i < 2048; i += 256) {
        int f = i >> 6, m = i & 63;
        A1T[6144 + i] = res_W[m * 32 + f];                                              // resW^T
    }
    for (int i = tid; i < 12288; i += 256) {
        int kk = i >> 6, o = i & 63;             // kk = c*3+dt
        A2T[i] = time_W[o * 192 + kk];
    }
    if (tid < 64) {
        BIAS[tid]       = cheb_b[tid];
        BIAS[64  + tid] = time_b[tid] + res_b[tid];
        BIAS[128 + tid] = ln_g[tid];
        BIAS[192 + tid] = ln_b[tid];
    }
    __syncthreads();

    int sub = tid >> 6;          // pair lane 0..3
    int l   = tid & 63;
    int tm  = (l & 15) << 2;     // output-channel tile base (0..60)
    int tn  = (l >> 4) << 2;     // time tile base (0,4,8,12)
    float* PR = PAIR + sub * 1536;

    for (int it = 0; it < ITERS; it++) {
        int p = blockIdx.x * (4 * ITERS) + it * 4 + sub;   // pair id = b*NN + n
        size_t inoff = (size_t)p * NODE_FLOATS;

        __syncthreads();   // previous iteration fully done with PR

        // ---- stage B1 = [x; Tx1; P2] (96 rows x 16 t) ----
        {
            const float4* xs4 = reinterpret_cast<const float4*>(x + inoff);
            const float4* t14 = reinterpret_cast<const float4*>(d_Tx1 + inoff);
            const float4* p24 = reinterpret_cast<const float4*>(d_P2 + inoff);
            float4* PR4 = reinterpret_cast<float4*>(PR);
            PR4[l]       = xs4[l];   PR4[64  + l] = xs4[64 + l];
            PR4[128 + l] = t14[l];   PR4[192 + l] = t14[64 + l];
            PR4[256 + l] = p24[l];   PR4[320 + l] = p24[64 + l];
        }
        __syncthreads();

        // ---- G1 (cheb, K=96) + G3 (residual, K=32) ----
        float acc[4][4];
        float accr[4][4];
#pragma unroll
        for (int i = 0; i < 4; i++)
#pragma unroll
            for (int j = 0; j < 4; j++) { acc[i][j] = 0.f; accr[i][j] = 0.f; }

#pragma unroll 4
        for (int k = 0; k < 96; k++) {
            float4 a  = *reinterpret_cast<const float4*>(A1T + k * 64 + tm);
            float4 bq = *reinterpret_cast<const float4*>(PR  + k * 16 + tn);
            float av[4] = {a.x, a.y, a.z, a.w};
            float bv[4] = {bq.x, bq.y, bq.z, bq.w};
#pragma unroll
            for (int i = 0; i < 4; i++)
#pragma unroll
                for (int j = 0; j < 4; j++)
                    acc[i][j] = fmaf(av[i], bv[j], acc[i][j]);
        }
#pragma unroll 4
        for (int k = 0; k < 32; k++) {
            float4 a  = *reinterpret_cast<const float4*>(A1T + (96 + k) * 64 + tm);
            float4 bq = *reinterpret_cast<const float4*>(PR  + k * 16 + tn);
            float av[4] = {a.x, a.y, a.z, a.w};
            float bv[4] = {bq.x, bq.y, bq.z, bq.w};
#pragma unroll
            for (int i = 0; i < 4; i++)
#pragma unroll
                for (int j = 0; j < 4; j++)
                    accr[i][j] = fmaf(av[i], bv[j], accr[i][j]);
        }
        __syncthreads();   // everyone done reading PR (B1) before aliasing with sPad

        // ---- s = relu(acc + cheb_b) into padded smem tile sPad[64][24], t at +4 ----
#pragma unroll
        for (int i = 0; i < 4; i++) {
            float cb = BIAS[tm + i];
            float4 v;
            v.x = fmaxf(acc[i][0] + cb, 0.f);
            v.y = fmaxf(acc[i][1] + cb, 0.f);
            v.z = fmaxf(acc[i][2] + cb, 0.f);
            v.w = fmaxf(acc[i][3] + cb, 0.f);
            *reinterpret_cast<float4*>(PR + (tm + i) * 24 + 4 + tn) = v;
        }
        // zero halo (t = -1 at idx 3, t = 16 at idx 20)
        PR[l * 24 + 3]  = 0.f;
        PR[l * 24 + 20] = 0.f;
        __syncthreads();

        // ---- G2: temporal conv (K = 64 channels x 3 taps) ----
        float z[4][4];
#pragma unroll
        for (int i = 0; i < 4; i++) {
            float zb0 = BIAS[64 + tm + i];
#pragma unroll
            for (int j = 0; j < 4; j++) z[i][j] = accr[i][j] + zb0;
        }
#pragma unroll 2
        for (int c2 = 0; c2 < 64; c2++) {
            const float* aw = A2T + c2 * 192 + tm;
            float4 a0 = *reinterpret_cast<const float4*>(aw);
            float4 a1 = *reinterpret_cast<const float4*>(aw + 64);
            float4 a2 = *reinterpret_cast<const float4*>(aw + 128);
            const float* sp = PR + c2 * 24 + 3 + tn;
            float sv[6];
#pragma unroll
            for (int r = 0; r < 6; r++) sv[r] = sp[r];
            float a0v[4] = {a0.x, a0.y, a0.z, a0.w};
            float a1v[4] = {a1.x, a1.y, a1.z, a1.w};
            float a2v[4] = {a2.x, a2.y, a2.z, a2.w};
#pragma unroll
            for (int i = 0; i < 4; i++)
#pragma unroll
                for (int j = 0; j < 4; j++) {
                    z[i][j] = fmaf(a0v[i], sv[j],     z[i][j]);
                    z[i][j] = fmaf(a1v[i], sv[j + 1], z[i][j]);
                    z[i][j] = fmaf(a2v[i], sv[j + 2], z[i][j]);
                }
        }
        // relu
#pragma unroll
        for (int i = 0; i < 4; i++)
#pragma unroll
            for (int j = 0; j < 4; j++) z[i][j] = fmaxf(z[i][j], 0.f);

        // ---- LayerNorm over 64 channels per t (reduce across 16 lanes sharing tn) ----
        float s1[4], s2[4];
#pragma unroll
        for (int j = 0; j < 4; j++) {
            s1[j] = z[0][j] + z[1][j] + z[2][j] + z[3][j];
            s2[j] = z[0][j]*z[0][j] + z[1][j]*z[1][j] + z[2][j]*z[2][j] + z[3][j]*z[3][j];
        }
#pragma unroll
        for (int off = 1; off < 16; off <<= 1) {
#pragma unroll
            for (int j = 0; j < 4; j++) {
                s1[j] += __shfl_xor_sync(0xffffffffu, s1[j], off);
                s2[j] += __shfl_xor_sync(0xffffffffu, s2[j], off);
            }
        }
        float mu[4], rs[4];
#pragma unroll
        for (int j = 0; j < 4; j++) {
            mu[j] = s1[j] * 0.015625f;
            float var = fmaf(-mu[j], mu[j], s2[j] * 0.015625f);
            rs[j] = rsqrtf(var + 1e-5f);
        }

        // ---- scale/shift + store out[b][n][o][t] ----
        float* op = out + (size_t)p * (CC * TT);
#pragma unroll
        for (int i = 0; i < 4; i++) {
            float g  = BIAS[128 + tm + i];
            float be = BIAS[192 + tm + i];
            float4 w;
            w.x = fmaf((z[i][0] - mu[0]) * rs[0], g, be);
            w.y = fmaf((z[i][1] - mu[1]) * rs[1], g, be);
            w.z = fmaf((z[i][2] - mu[2]) * rs[2], g, be);
            w.w = fmaf((z[i][3] - mu[3]) * rs[3], g, be);
            *reinterpret_cast<float4*>(op + (tm + i) * 16 + tn) = w;
        }
    }
}

// ---------------- launch ----------------
extern "C" void kernel_launch(void* const* d_in, const int* in_sizes, int n_in,
                              void* d_out, int out_size) {
    const float* x       = (const float*)d_in[0];
    const int*   edge    = (const int*)  d_in[1];
    const float* cheb_W  = (const float*)d_in[2];
    const float* cheb_b  = (const float*)d_in[3];
    const float* time_W  = (const float*)d_in[4];
    const float* time_b  = (const float*)d_in[5];
    const float* res_W   = (const float*)d_in[6];
    const float* res_b   = (const float*)d_in[7];
    const float* ln_g    = (const float*)d_in[8];
    const float* ln_b    = (const float*)d_in[9];
    float* out = (float*)d_out;

    const int* row = edge;
    const int* col = edge + EE;

    cudaFuncSetAttribute(fused_kernel, cudaFuncAttributeMaxDynamicSharedMemorySize, SMEM_BYTES);

    // CSR build
    zero_counts_kernel<<<(NN + 255) / 256, 256>>>();
    count_kernel<<<(EE + 255) / 256, 256>>>(row, col);
    dinv_kernel<<<(NN + 255) / 256, 256>>>();
    scan_kernel<<<1, 1024>>>();
    fill_kernel<<<(EE + 255) / 256, 256>>>(row, col);

    // Chebyshev propagations
    float* Tx1p; cudaGetSymbolAddress((void**)&Tx1p, d_Tx1);
    float* P2p;  cudaGetSymbolAddress((void**)&P2p,  d_P2);
    prop_kernel<<<NN, 256>>>(x, Tx1p);
    prop_kernel<<<NN, 256>>>(Tx1p, P2p);

    // Fused cheb-combine + temporal conv + residual + relu + LayerNorm
    fused_kernel<<<FUSED_GRID, 256, SMEM_BYTES>>>(
        x, cheb_W, cheb_b, time_W, time_b, res_W, res_b, ln_g, ln_b, out);
}

// round 2
// speedup vs baseline: 1.0757x; 1.0757x over previous
#include <cuda_runtime.h>
#include <cstdint>
#include <cstddef>

#define NN 10000
#define EE 160000
#define BB 2
#define FIN 32
#define TT 16
#define CC 64
#define PAIRS (BB*NN)          // 20000
#define NODE_FLOATS (FIN*TT)   // 512 per (b,n)

// ---------------- device scratch (no allocs allowed) ----------------
__device__ float d_Tx1[(size_t)PAIRS * NODE_FLOATS];  // L x
__device__ float d_P2 [(size_t)PAIRS * NODE_FLOATS];  // L (L x)
__device__ int   d_degc[NN];
__device__ float d_dinv[NN];
__device__ int   d_cnt[NN];
__device__ int   d_ptr[NN + 1];
__device__ int   d_wr[NN];
__device__ int   d_csrc[EE];
__device__ float d_csw[EE];

// ---------------- packed fp32x2 helpers ----------------
__device__ __forceinline__ unsigned long long pack2(float a, float b) {
    unsigned long long r;
    asm("mov.b64 %0, {%1, %2};" : "=l"(r)
        : "r"(__float_as_uint(a)), "r"(__float_as_uint(b)));
    return r;
}
__device__ __forceinline__ unsigned long long packdup(float a) {
    unsigned long long r;
    unsigned int u = __float_as_uint(a);
    asm("mov.b64 %0, {%1, %2};" : "=l"(r) : "r"(u), "r"(u));
    return r;
}
__device__ __forceinline__ unsigned long long fma2(unsigned long long a,
                                                   unsigned long long b,
                                                   unsigned long long c) {
    unsigned long long d;
    asm("fma.rn.f32x2 %0, %1, %2, %3;" : "=l"(d) : "l"(a), "l"(b), "l"(c));
    return d;
}
__device__ __forceinline__ unsigned long long add2(unsigned long long a,
                                                   unsigned long long b) {
    unsigned long long d;
    asm("add.rn.f32x2 %0, %1, %2;" : "=l"(d) : "l"(a), "l"(b));
    return d;
}
__device__ __forceinline__ float2 unpack2(unsigned long long p) {
    unsigned int x, y;
    asm("mov.b64 {%0, %1}, %2;" : "=r"(x), "=r"(y) : "l"(p));
    return make_float2(__uint_as_float(x), __uint_as_float(y));
}

// ---------------- CSR build ----------------
__global__ void zero_counts_kernel() {
    int i = blockIdx.x * blockDim.x + threadIdx.x;
    if (i < NN) { d_degc[i] = 0; d_cnt[i] = 0; }
}

__global__ void count_kernel(const int* __restrict__ row, const int* __restrict__ col) {
    int e = blockIdx.x * blockDim.x + threadIdx.x;
    if (e < EE) {
        atomicAdd(&d_degc[row[e]], 1);
        atomicAdd(&d_cnt[col[e]], 1);
    }
}

__global__ void dinv_kernel() {
    int i = blockIdx.x * blockDim.x + threadIdx.x;
    if (i < NN) {
        int d = d_degc[i];
        d_dinv[i] = (d > 0) ? rsqrtf((float)d) : 0.f;
    }
}

// shfl-based block scan: 1024 threads, 10 chunks
__global__ void scan_kernel() {
    __shared__ int wsum[32];
    __shared__ int carry;
    int tid = threadIdx.x, lane = tid & 31, wid = tid >> 5;
    if (tid == 0) carry = 0;
    __syncthreads();
    for (int base = 0; base < NN; base += 1024) {
        int i = base + tid;
        int v = (i < NN) ? d_cnt[i] : 0;
        int s = v;
#pragma unroll
        for (int off = 1; off < 32; off <<= 1) {
            int t = __shfl_up_sync(0xffffffffu, s, off);
            if (lane >= off) s += t;
        }
        if (lane == 31) wsum[wid] = s;
        __syncthreads();
        if (wid == 0) {
            int ws = wsum[lane];
#pragma unroll
            for (int off = 1; off < 32; off <<= 1) {
                int t = __shfl_up_sync(0xffffffffu, ws, off);
                if (lane >= off) ws += t;
            }
            wsum[lane] = ws;
        }
        __syncthreads();
        int incl = s + ((wid > 0) ? wsum[wid - 1] : 0);
        int c0 = carry;
        if (i < NN) { int ex = c0 + incl - v; d_ptr[i] = ex; d_wr[i] = ex; }
        __syncthreads();
        if (tid == 1023) carry = c0 + incl;
        __syncthreads();
    }
    if (threadIdx.x == 0) d_ptr[NN] = carry;
}

__global__ void fill_kernel(const int* __restrict__ row, const int* __restrict__ col) {
    int e = blockIdx.x * blockDim.x + threadIdx.x;
    if (e < EE) {
        int r = row[e], c = col[e];
        float wv = -(d_dinv[r] * d_dinv[c]);
        int pos = atomicAdd(&d_wr[c], 1);
        d_csrc[pos] = r;
        d_csw[pos]  = wv;
    }
}

// ---------------- propagation: out[n] = sum_{e: col=n} w_e * z[src_e] ----------------
__global__ __launch_bounds__(256) void prop_kernel(const float* __restrict__ z,
                                                   float* __restrict__ outp) {
    int n = blockIdx.x;
    int tid = threadIdx.x;
    int b = tid >> 7;        // 0..1
    int q = tid & 127;       // float4 index within (F,T)=512 floats
    const float4* zb = reinterpret_cast<const float4*>(z) + (size_t)b * NN * 128;
    float4 acc = make_float4(0.f, 0.f, 0.f, 0.f);
    int s = d_ptr[n], e = d_ptr[n + 1];
    int k = s;
    for (; k + 1 < e; k += 2) {
        int u0 = d_csrc[k], u1 = d_csrc[k + 1];
        float w0 = d_csw[k], w1 = d_csw[k + 1];
        float4 v0 = zb[(size_t)u0 * 128 + q];
        float4 v1 = zb[(size_t)u1 * 128 + q];
        acc.x += w0 * v0.x + w1 * v1.x;
        acc.y += w0 * v0.y + w1 * v1.y;
        acc.z += w0 * v0.z + w1 * v1.z;
        acc.w += w0 * v0.w + w1 * v1.w;
    }
    if (k < e) {
        int u0 = d_csrc[k];
        float w0 = d_csw[k];
        float4 v0 = zb[(size_t)u0 * 128 + q];
        acc.x += w0 * v0.x; acc.y += w0 * v0.y;
        acc.z += w0 * v0.z; acc.w += w0 * v0.w;
    }
    reinterpret_cast<float4*>(outp)[(size_t)b * NN * 128 + (size_t)n * 128 + q] = acc;
}

// ---------------- fused dense kernel (FFMA2 inner loops) ----------------
#define SM_A1T   0
#define SM_A2T   8192
#define SM_BIAS  20480
#define SM_PAIR  20736
#define SM_FLOATS 26880
#define SMEM_BYTES (SM_FLOATS * 4)
#define ITERS 4
#define FUSED_GRID 1250   // 1250 * 4 * 4 = 20000 pairs

__global__ __launch_bounds__(256, 2) void fused_kernel(
    const float* __restrict__ x,
    const float* __restrict__ cheb_W,   // (3,32,64)
    const float* __restrict__ cheb_b,   // (64)
    const float* __restrict__ time_W,   // (64,64,1,3)
    const float* __restrict__ time_b,   // (64)
    const float* __restrict__ res_W,    // (64,32)
    const float* __restrict__ res_b,    // (64)
    const float* __restrict__ ln_g,     // (64)
    const float* __restrict__ ln_b,     // (64)
    float* __restrict__ out)            // (B,N,64,16)
{
    extern __shared__ float smf[];
    float* A1T  = smf + SM_A1T;    // [128][64]  rows 0..95 cheb-folded, 96..127 resW^T
    float* A2T  = smf + SM_A2T;    // [192][64]  (c*3+dt)-major, o contiguous
    float* BIAS = smf + SM_BIAS;   // chb[64] zb[64] lng[64] lnb[64]
    float* PAIR = smf + SM_PAIR;   // 4 * 1536

    int tid = threadIdx.x;

    for (int i = tid; i < 2048; i += 256) A1T[i]        = cheb_W[i] - cheb_W[4096 + i]; // W0 - W2
    for (int i = tid; i < 2048; i += 256) A1T[2048 + i] = cheb_W[2048 + i];             // W1
    for (int i = tid; i < 2048; i += 256) A1T[4096 + i] = 2.f * cheb_W[4096 + i];       // 2*W2
    for (int i = tid; i < 2048; i += 256) {
        int f = i >> 6, m = i & 63;
        A1T[6144 + i] = res_W[m * 32 + f];                                              // resW^T
    }
    for (int i = tid; i < 12288; i += 256) {
        int kk = i >> 6, o = i & 63;             // kk = c*3+dt
        A2T[i] = time_W[o * 192 + kk];
    }
    if (tid < 64) {
        BIAS[tid]       = cheb_b[tid];
        BIAS[64  + tid] = time_b[tid] + res_b[tid];
        BIAS[128 + tid] = ln_g[tid];
        BIAS[192 + tid] = ln_b[tid];
    }
    __syncthreads();

    int sub = tid >> 6;          // pair lane 0..3
    int l   = tid & 63;
    int tm  = (l & 15) << 2;     // output-channel tile base (0..60)
    int tn  = (l >> 4) << 2;     // time tile base (0,4,8,12)
    float* PR = PAIR + sub * 1536;

    for (int it = 0; it < ITERS; it++) {
        int p = blockIdx.x * (4 * ITERS) + it * 4 + sub;   // pair id = b*NN + n
        size_t inoff = (size_t)p * NODE_FLOATS;

        __syncthreads();   // previous iteration fully done with PR

        // ---- stage B1 = [x; Tx1; P2] (96 rows x 16 t) ----
        {
            const float4* xs4 = reinterpret_cast<const float4*>(x + inoff);
            const float4* t14 = reinterpret_cast<const float4*>(d_Tx1 + inoff);
            const float4* p24 = reinterpret_cast<const float4*>(d_P2 + inoff);
            float4* PR4 = reinterpret_cast<float4*>(PR);
            PR4[l]       = xs4[l];   PR4[64  + l] = xs4[64 + l];
            PR4[128 + l] = t14[l];   PR4[192 + l] = t14[64 + l];
            PR4[256 + l] = p24[l];   PR4[320 + l] = p24[64 + l];
        }
        __syncthreads();

        // ---- G1 (cheb, K=96) + G3 (residual, K=32), packed channel pairs ----
        // acc2[ip][j]: channels (tm+2ip, tm+2ip+1), time tn+j
        unsigned long long acc2[2][4], accr2[2][4];
#pragma unroll
        for (int ip = 0; ip < 2; ip++)
#pragma unroll
            for (int j = 0; j < 4; j++) { acc2[ip][j] = 0ull; accr2[ip][j] = 0ull; }

#pragma unroll 4
        for (int k = 0; k < 96; k++) {
            ulonglong2 a = *reinterpret_cast<const ulonglong2*>(A1T + k * 64 + tm);
            float4 bq = *reinterpret_cast<const float4*>(PR + k * 16 + tn);
            unsigned long long b0 = packdup(bq.x), b1 = packdup(bq.y);
            unsigned long long b2 = packdup(bq.z), b3 = packdup(bq.w);
            acc2[0][0] = fma2(a.x, b0, acc2[0][0]);
            acc2[1][0] = fma2(a.y, b0, acc2[1][0]);
            acc2[0][1] = fma2(a.x, b1, acc2[0][1]);
            acc2[1][1] = fma2(a.y, b1, acc2[1][1]);
            acc2[0][2] = fma2(a.x, b2, acc2[0][2]);
            acc2[1][2] = fma2(a.y, b2, acc2[1][2]);
            acc2[0][3] = fma2(a.x, b3, acc2[0][3]);
            acc2[1][3] = fma2(a.y, b3, acc2[1][3]);
        }
#pragma unroll 4
        for (int k = 0; k < 32; k++) {
            ulonglong2 a = *reinterpret_cast<const ulonglong2*>(A1T + (96 + k) * 64 + tm);
            float4 bq = *reinterpret_cast<const float4*>(PR + k * 16 + tn);
            unsigned long long b0 = packdup(bq.x), b1 = packdup(bq.y);
            unsigned long long b2 = packdup(bq.z), b3 = packdup(bq.w);
            accr2[0][0] = fma2(a.x, b0, accr2[0][0]);
            accr2[1][0] = fma2(a.y, b0, accr2[1][0]);
            accr2[0][1] = fma2(a.x, b1, accr2[0][1]);
            accr2[1][1] = fma2(a.y, b1, accr2[1][1]);
            accr2[0][2] = fma2(a.x, b2, accr2[0][2]);
            accr2[1][2] = fma2(a.y, b2, accr2[1][2]);
            accr2[0][3] = fma2(a.x, b3, accr2[0][3]);
            accr2[1][3] = fma2(a.y, b3, accr2[1][3]);
        }
        __syncthreads();   // everyone done reading PR (B1) before aliasing with sPad

        // ---- s = relu(acc + cheb_b) into padded smem tile sPad[64][24], t at +4 ----
#pragma unroll
        for (int ip = 0; ip < 2; ip++) {
            float2 u0 = unpack2(acc2[ip][0]);
            float2 u1 = unpack2(acc2[ip][1]);
            float2 u2 = unpack2(acc2[ip][2]);
            float2 u3 = unpack2(acc2[ip][3]);
            int c0 = tm + 2 * ip;
            float cb0 = BIAS[c0], cb1 = BIAS[c0 + 1];
            float4 v0, v1;
            v0.x = fmaxf(u0.x + cb0, 0.f); v0.y = fmaxf(u1.x + cb0, 0.f);
            v0.z = fmaxf(u2.x + cb0, 0.f); v0.w = fmaxf(u3.x + cb0, 0.f);
            v1.x = fmaxf(u0.y + cb1, 0.f); v1.y = fmaxf(u1.y + cb1, 0.f);
            v1.z = fmaxf(u2.y + cb1, 0.f); v1.w = fmaxf(u3.y + cb1, 0.f);
            *reinterpret_cast<float4*>(PR + c0 * 24 + 4 + tn)       = v0;
            *reinterpret_cast<float4*>(PR + (c0 + 1) * 24 + 4 + tn) = v1;
        }
        // zero halo (t = -1 at idx 3, t = 16 at idx 20)
        PR[l * 24 + 3]  = 0.f;
        PR[l * 24 + 20] = 0.f;
        __syncthreads();

        // ---- G2: temporal conv (K = 64 channels x 3 taps), packed channel pairs ----
        unsigned long long z2[2][4];
        {
            unsigned long long zb0 = pack2(BIAS[64 + tm],     BIAS[64 + tm + 1]);
            unsigned long long zb1 = pack2(BIAS[64 + tm + 2], BIAS[64 + tm + 3]);
#pragma unroll
            for (int j = 0; j < 4; j++) {
                z2[0][j] = add2(accr2[0][j], zb0);
                z2[1][j] = add2(accr2[1][j], zb1);
            }
        }
#pragma unroll 2
        for (int c2 = 0; c2 < 64; c2++) {
            const float* aw = A2T + c2 * 192 + tm;
            ulonglong2 A0 = *reinterpret_cast<const ulonglong2*>(aw);
            ulonglong2 A1 = *reinterpret_cast<const ulonglong2*>(aw + 64);
            ulonglong2 A2 = *reinterpret_cast<const ulonglong2*>(aw + 128);
            const float* sp = PR + c2 * 24 + 3 + tn;
            unsigned long long sv[6];
#pragma unroll
            for (int r = 0; r < 6; r++) sv[r] = packdup(sp[r]);
#pragma unroll
            for (int j = 0; j < 4; j++) {
                z2[0][j] = fma2(A0.x, sv[j],     z2[0][j]);
                z2[1][j] = fma2(A0.y, sv[j],     z2[1][j]);
                z2[0][j] = fma2(A1.x, sv[j + 1], z2[0][j]);
                z2[1][j] = fma2(A1.y, sv[j + 1], z2[1][j]);
                z2[0][j] = fma2(A2.x, sv[j + 2], z2[0][j]);
                z2[1][j] = fma2(A2.y, sv[j + 2], z2[1][j]);
            }
        }

        // unpack + relu
        float z[4][4];
#pragma unroll
        for (int ip = 0; ip < 2; ip++)
#pragma unroll
            for (int j = 0; j < 4; j++) {
                float2 u = unpack2(z2[ip][j]);
                z[2 * ip][j]     = fmaxf(u.x, 0.f);
                z[2 * ip + 1][j] = fmaxf(u.y, 0.f);
            }

        // ---- LayerNorm over 64 channels per t (reduce across 16 lanes sharing tn) ----
        float s1[4], s2[4];
#pragma unroll
        for (int j = 0; j < 4; j++) {
            s1[j] = z[0][j] + z[1][j] + z[2][j] + z[3][j];
            s2[j] = z[0][j]*z[0][j] + z[1][j]*z[1][j] + z[2][j]*z[2][j] + z[3][j]*z[3][j];
        }
#pragma unroll
        for (int off = 1; off < 16; off <<= 1) {
#pragma unroll
            for (int j = 0; j < 4; j++) {
                s1[j] += __shfl_xor_sync(0xffffffffu, s1[j], off);
                s2[j] += __shfl_xor_sync(0xffffffffu, s2[j], off);
            }
        }
        float mu[4], rs[4];
#pragma unroll
        for (int j = 0; j < 4; j++) {
            mu[j] = s1[j] * 0.015625f;
            float var = fmaf(-mu[j], mu[j], s2[j] * 0.015625f);
            rs[j] = rsqrtf(var + 1e-5f);
        }

        // ---- scale/shift + store out[b][n][o][t] ----
        float* op = out + (size_t)p * (CC * TT);
#pragma unroll
        for (int i = 0; i < 4; i++) {
            float g  = BIAS[128 + tm + i];
            float be = BIAS[192 + tm + i];
            float4 w;
            w.x = fmaf((z[i][0] - mu[0]) * rs[0], g, be);
            w.y = fmaf((z[i][1] - mu[1]) * rs[1], g, be);
            w.z = fmaf((z[i][2] - mu[2]) * rs[2], g, be);
            w.w = fmaf((z[i][3] - mu[3]) * rs[3], g, be);
            *reinterpret_cast<float4*>(op + (tm + i) * 16 + tn) = w;
        }
    }
}

// ---------------- launch ----------------
extern "C" void kernel_launch(void* const* d_in, const int* in_sizes, int n_in,
                              void* d_out, int out_size) {
    const float* x       = (const float*)d_in[0];
    const int*   edge    = (const int*)  d_in[1];
    const float* cheb_W  = (const float*)d_in[2];
    const float* cheb_b  = (const float*)d_in[3];
    const float* time_W  = (const float*)d_in[4];
    const float* time_b  = (const float*)d_in[5];
    const float* res_W   = (const float*)d_in[6];
    const float* res_b   = (const float*)d_in[7];
    const float* ln_g    = (const float*)d_in[8];
    const float* ln_b    = (const float*)d_in[9];
    float* out = (float*)d_out;

    const int* row = edge;
    const int* col = edge + EE;

    cudaFuncSetAttribute(fused_kernel, cudaFuncAttributeMaxDynamicSharedMemorySize, SMEM_BYTES);

    // CSR build
    zero_counts_kernel<<<(NN + 255) / 256, 256>>>();
    count_kernel<<<(EE + 255) / 256, 256>>>(row, col);
    dinv_kernel<<<(NN + 255) / 256, 256>>>();
    scan_kernel<<<1, 1024>>>();
    fill_kernel<<<(EE + 255) / 256, 256>>>(row, col);

    // Chebyshev propagations
    float* Tx1p; cudaGetSymbolAddress((void**)&Tx1p, d_Tx1);
    float* P2p;  cudaGetSymbolAddress((void**)&P2p,  d_P2);
    prop_kernel<<<NN, 256>>>(x, Tx1p);
    prop_kernel<<<NN, 256>>>(Tx1p, P2p);

    // Fused cheb-combine + temporal conv + residual + relu + LayerNorm
    fused_kernel<<<FUSED_GRID, 256, SMEM_BYTES>>>(
        x, cheb_W, cheb_b, time_W, time_b, res_W, res_b, ln_g, ln_b, out);
}

// round 3
// speedup vs baseline: 1.0789x; 1.0030x over previous
#include <cuda_runtime.h>
#include <cstdint>
#include <cstddef>

#define NN 10000
#define EE 160000
#define BB 2
#define FIN 32
#define TT 16
#define CC 64
#define PAIRS (BB*NN)          // 20000
#define NODE_FLOATS (FIN*TT)   // 512 per (b,n)

// ---------------- device scratch (no allocs allowed) ----------------
__device__ float d_Tx1[(size_t)PAIRS * NODE_FLOATS];  // L x
__device__ float d_P2 [(size_t)PAIRS * NODE_FLOATS];  // L (L x)
__device__ int   d_degc[NN];
__device__ float d_dinv[NN];
__device__ int   d_cnt[NN];
__device__ int   d_ptr[NN + 1];
__device__ int   d_wr[NN];
__device__ int   d_csrc[EE];
__device__ float d_csw[EE];

// ---------------- packed fp32x2 helpers ----------------
__device__ __forceinline__ unsigned long long pack2(float a, float b) {
    unsigned long long r;
    asm("mov.b64 %0, {%1, %2};" : "=l"(r)
        : "r"(__float_as_uint(a)), "r"(__float_as_uint(b)));
    return r;
}
__device__ __forceinline__ unsigned long long packdup(float a) {
    unsigned long long r;
    unsigned int u = __float_as_uint(a);
    asm("mov.b64 %0, {%1, %2};" : "=l"(r) : "r"(u), "r"(u));
    return r;
}
__device__ __forceinline__ unsigned long long fma2(unsigned long long a,
                                                   unsigned long long b,
                                                   unsigned long long c) {
    unsigned long long d;
    asm("fma.rn.f32x2 %0, %1, %2, %3;" : "=l"(d) : "l"(a), "l"(b), "l"(c));
    return d;
}
__device__ __forceinline__ unsigned long long add2(unsigned long long a,
                                                   unsigned long long b) {
    unsigned long long d;
    asm("add.rn.f32x2 %0, %1, %2;" : "=l"(d) : "l"(a), "l"(b));
    return d;
}
__device__ __forceinline__ float2 unpack2(unsigned long long p) {
    unsigned int x, y;
    asm("mov.b64 {%0, %1}, %2;" : "=r"(x), "=r"(y) : "l"(p));
    return make_float2(__uint_as_float(x), __uint_as_float(y));
}

// ---------------- CSR build ----------------
__global__ void zero_counts_kernel() {
    int i = blockIdx.x * blockDim.x + threadIdx.x;
    if (i < NN) { d_degc[i] = 0; d_cnt[i] = 0; }
}

__global__ void count_kernel(const int* __restrict__ row, const int* __restrict__ col) {
    int e = blockIdx.x * blockDim.x + threadIdx.x;
    if (e < EE) {
        atomicAdd(&d_degc[row[e]], 1);
        atomicAdd(&d_cnt[col[e]], 1);
    }
}

__global__ void dinv_kernel() {
    int i = blockIdx.x * blockDim.x + threadIdx.x;
    if (i < NN) {
        int d = d_degc[i];
        d_dinv[i] = (d > 0) ? rsqrtf((float)d) : 0.f;
    }
}

// shfl-based block scan: 1024 threads, 10 chunks
__global__ void scan_kernel() {
    __shared__ int wsum[32];
    __shared__ int carry;
    int tid = threadIdx.x, lane = tid & 31, wid = tid >> 5;
    if (tid == 0) carry = 0;
    __syncthreads();
    for (int base = 0; base < NN; base += 1024) {
        int i = base + tid;
        int v = (i < NN) ? d_cnt[i] : 0;
        int s = v;
#pragma unroll
        for (int off = 1; off < 32; off <<= 1) {
            int t = __shfl_up_sync(0xffffffffu, s, off);
            if (lane >= off) s += t;
        }
        if (lane == 31) wsum[wid] = s;
        __syncthreads();
        if (wid == 0) {
            int ws = wsum[lane];
#pragma unroll
            for (int off = 1; off < 32; off <<= 1) {
                int t = __shfl_up_sync(0xffffffffu, ws, off);
                if (lane >= off) ws += t;
            }
            wsum[lane] = ws;
        }
        __syncthreads();
        int incl = s + ((wid > 0) ? wsum[wid - 1] : 0);
        int c0 = carry;
        if (i < NN) { int ex = c0 + incl - v; d_ptr[i] = ex; d_wr[i] = ex; }
        __syncthreads();
        if (tid == 1023) carry = c0 + incl;
        __syncthreads();
    }
    if (threadIdx.x == 0) d_ptr[NN] = carry;
}

__global__ void fill_kernel(const int* __restrict__ row, const int* __restrict__ col) {
    int e = blockIdx.x * blockDim.x + threadIdx.x;
    if (e < EE) {
        int r = row[e], c = col[e];
        float wv = -(d_dinv[r] * d_dinv[c]);
        int pos = atomicAdd(&d_wr[c], 1);
        d_csrc[pos] = r;
        d_csw[pos]  = wv;
    }
}

// ---------------- propagation: out[n] = sum_{e: col=n} w_e * z[src_e] ----------------
__global__ __launch_bounds__(256) void prop_kernel(const float* __restrict__ z,
                                                   float* __restrict__ outp) {
    int n = blockIdx.x;
    int tid = threadIdx.x;
    int b = tid >> 7;        // 0..1
    int q = tid & 127;       // float4 index within (F,T)=512 floats
    const float4* zb = reinterpret_cast<const float4*>(z) + (size_t)b * NN * 128;
    float4 acc = make_float4(0.f, 0.f, 0.f, 0.f);
    int s = d_ptr[n], e = d_ptr[n + 1];
    int k = s;
    for (; k + 1 < e; k += 2) {
        int u0 = d_csrc[k], u1 = d_csrc[k + 1];
        float w0 = d_csw[k], w1 = d_csw[k + 1];
        float4 v0 = zb[(size_t)u0 * 128 + q];
        float4 v1 = zb[(size_t)u1 * 128 + q];
        acc.x += w0 * v0.x + w1 * v1.x;
        acc.y += w0 * v0.y + w1 * v1.y;
        acc.z += w0 * v0.z + w1 * v1.z;
        acc.w += w0 * v0.w + w1 * v1.w;
    }
    if (k < e) {
        int u0 = d_csrc[k];
        float w0 = d_csw[k];
        float4 v0 = zb[(size_t)u0 * 128 + q];
        acc.x += w0 * v0.x; acc.y += w0 * v0.y;
        acc.z += w0 * v0.z; acc.w += w0 * v0.w;
    }
    reinterpret_cast<float4*>(outp)[(size_t)b * NN * 128 + (size_t)n * 128 + q] = acc;
}

// ---------------- fused dense kernel (FFMA2 inner loops) ----------------
#define SM_A1T   0
#define SM_A2T   8192
#define SM_BIAS  20480
#define SM_PAIR  20736
#define SM_FLOATS 26880
#define SMEM_BYTES (SM_FLOATS * 4)
#define ITERS 4
#define FUSED_GRID 1250   // 1250 * 4 * 4 = 20000 pairs

__global__ __launch_bounds__(256, 2) void fused_kernel(
    const float* __restrict__ x,
    const float* __restrict__ cheb_W,   // (3,32,64)
    const float* __restrict__ cheb_b,   // (64)
    const float* __restrict__ time_W,   // (64,64,1,3)
    const float* __restrict__ time_b,   // (64)
    const float* __restrict__ res_W,    // (64,32)
    const float* __restrict__ res_b,    // (64)
    const float* __restrict__ ln_g,     // (64)
    const float* __restrict__ ln_b,     // (64)
    float* __restrict__ out)            // (B,N,64,16)
{
    extern __shared__ float smf[];
    float* A1T  = smf + SM_A1T;    // [128][64]  rows 0..95 cheb-folded, 96..127 resW^T
    float* A2T  = smf + SM_A2T;    // [192][64]  (c*3+dt)-major, o contiguous
    float* BIAS = smf + SM_BIAS;   // chb[64] zb[64] lng[64] lnb[64]
    float* PAIR = smf + SM_PAIR;   // 4 * 1536

    int tid = threadIdx.x;

    for (int i = tid; i < 2048; i += 256) A1T[i]        = cheb_W[i] - cheb_W[4096 + i]; // W0 - W2
    for (int i = tid; i < 2048; i += 256) A1T[2048 + i] = cheb_W[2048 + i];             // W1
    for (int i = tid; i < 2048; i += 256) A1T[4096 + i] = 2.f * cheb_W[4096 + i];       // 2*W2
    for (int i = tid; i < 2048; i += 256) {
        int f = i >> 6, m = i & 63;
        A1T[6144 + i] = res_W[m * 32 + f];                                              // resW^T
    }
    for (int i = tid; i < 12288; i += 256) {
        int kk = i >> 6, o = i & 63;             // kk = c*3+dt
        A2T[i] = time_W[o * 192 + kk];
    }
    if (tid < 64) {
        BIAS[tid]       = cheb_b[tid];
        BIAS[64  + tid] = time_b[tid] + res_b[tid];
        BIAS[128 + tid] = ln_g[tid];
        BIAS[192 + tid] = ln_b[tid];
    }
    __syncthreads();

    int sub = tid >> 6;          // pair lane 0..3
    int l   = tid & 63;
    int tm  = (l & 15) << 2;     // output-channel tile base (0..60)
    int tn  = (l >> 4) << 2;     // time tile base (0,4,8,12)
    float* PR = PAIR + sub * 1536;

    for (int it = 0; it < ITERS; it++) {
        int p = blockIdx.x * (4 * ITERS) + it * 4 + sub;   // pair id = b*NN + n
        size_t inoff = (size_t)p * NODE_FLOATS;

        __syncthreads();   // previous iteration fully done with PR

        // ---- stage B1 = [x; Tx1; P2] (96 rows x 16 t) ----
        {
            const float4* xs4 = reinterpret_cast<const float4*>(x + inoff);
            const float4* t14 = reinterpret_cast<const float4*>(d_Tx1 + inoff);
            const float4* p24 = reinterpret_cast<const float4*>(d_P2 + inoff);
            float4* PR4 = reinterpret_cast<float4*>(PR);
            PR4[l]       = xs4[l];   PR4[64  + l] = xs4[64 + l];
            PR4[128 + l] = t14[l];   PR4[192 + l] = t14[64 + l];
            PR4[256 + l] = p24[l];   PR4[320 + l] = p24[64 + l];
        }
        __syncthreads();

        // ---- G1 (cheb, K=96) + G3 (residual, K=32), packed channel pairs ----
        // acc2[ip][j]: channels (tm+2ip, tm+2ip+1), time tn+j
        unsigned long long acc2[2][4], accr2[2][4];
#pragma unroll
        for (int ip = 0; ip < 2; ip++)
#pragma unroll
            for (int j = 0; j < 4; j++) { acc2[ip][j] = 0ull; accr2[ip][j] = 0ull; }

#pragma unroll 4
        for (int k = 0; k < 96; k++) {
            ulonglong2 a = *reinterpret_cast<const ulonglong2*>(A1T + k * 64 + tm);
            float4 bq = *reinterpret_cast<const float4*>(PR + k * 16 + tn);
            unsigned long long b0 = packdup(bq.x), b1 = packdup(bq.y);
            unsigned long long b2 = packdup(bq.z), b3 = packdup(bq.w);
            acc2[0][0] = fma2(a.x, b0, acc2[0][0]);
            acc2[1][0] = fma2(a.y, b0, acc2[1][0]);
            acc2[0][1] = fma2(a.x, b1, acc2[0][1]);
            acc2[1][1] = fma2(a.y, b1, acc2[1][1]);
            acc2[0][2] = fma2(a.x, b2, acc2[0][2]);
            acc2[1][2] = fma2(a.y, b2, acc2[1][2]);
            acc2[0][3] = fma2(a.x, b3, acc2[0][3]);
            acc2[1][3] = fma2(a.y, b3, acc2[1][3]);
        }
#pragma unroll 4
        for (int k = 0; k < 32; k++) {
            ulonglong2 a = *reinterpret_cast<const ulonglong2*>(A1T + (96 + k) * 64 + tm);
            float4 bq = *reinterpret_cast<const float4*>(PR + k * 16 + tn);
            unsigned long long b0 = packdup(bq.x), b1 = packdup(bq.y);
            unsigned long long b2 = packdup(bq.z), b3 = packdup(bq.w);
            accr2[0][0] = fma2(a.x, b0, accr2[0][0]);
            accr2[1][0] = fma2(a.y, b0, accr2[1][0]);
            accr2[0][1] = fma2(a.x, b1, accr2[0][1]);
            accr2[1][1] = fma2(a.y, b1, accr2[1][1]);
            accr2[0][2] = fma2(a.x, b2, accr2[0][2]);
            accr2[1][2] = fma2(a.y, b2, accr2[1][2]);
            accr2[0][3] = fma2(a.x, b3, accr2[0][3]);
            accr2[1][3] = fma2(a.y, b3, accr2[1][3]);
        }
        __syncthreads();   // everyone done reading PR (B1) before aliasing with sPad

        // ---- s = relu(acc + cheb_b) into padded smem tile sPad[64][24], t at +4 ----
#pragma unroll
        for (int ip = 0; ip < 2; ip++) {
            float2 u0 = unpack2(acc2[ip][0]);
            float2 u1 = unpack2(acc2[ip][1]);
            float2 u2 = unpack2(acc2[ip][2]);
            float2 u3 = unpack2(acc2[ip][3]);
            int c0 = tm + 2 * ip;
            float cb0 = BIAS[c0], cb1 = BIAS[c0 + 1];
            float4 v0, v1;
            v0.x = fmaxf(u0.x + cb0, 0.f); v0.y = fmaxf(u1.x + cb0, 0.f);
            v0.z = fmaxf(u2.x + cb0, 0.f); v0.w = fmaxf(u3.x + cb0, 0.f);
            v1.x = fmaxf(u0.y + cb1, 0.f); v1.y = fmaxf(u1.y + cb1, 0.f);
            v1.z = fmaxf(u2.y + cb1, 0.f); v1.w = fmaxf(u3.y + cb1, 0.f);
            *reinterpret_cast<float4*>(PR + c0 * 24 + 4 + tn)       = v0;
            *reinterpret_cast<float4*>(PR + (c0 + 1) * 24 + 4 + tn) = v1;
        }
        // zero halo (t = -1 at idx 3, t = 16 at idx 20)
        PR[l * 24 + 3]  = 0.f;
        PR[l * 24 + 20] = 0.f;
        __syncthreads();

        // ---- G2: temporal conv (K = 64 channels x 3 taps), packed channel pairs ----
        unsigned long long z2[2][4];
        {
            unsigned long long zb0 = pack2(BIAS[64 + tm],     BIAS[64 + tm + 1]);
            unsigned long long zb1 = pack2(BIAS[64 + tm + 2], BIAS[64 + tm + 3]);
#pragma unroll
            for (int j = 0; j < 4; j++) {
                z2[0][j] = add2(accr2[0][j], zb0);
                z2[1][j] = add2(accr2[1][j], zb1);
            }
        }
#pragma unroll 2
        for (int c2 = 0; c2 < 64; c2++) {
            const float* aw = A2T + c2 * 192 + tm;
            ulonglong2 A0 = *reinterpret_cast<const ulonglong2*>(aw);
            ulonglong2 A1 = *reinterpret_cast<const ulonglong2*>(aw + 64);
            ulonglong2 A2 = *reinterpret_cast<const ulonglong2*>(aw + 128);
            const float* sp = PR + c2 * 24 + 3 + tn;
            unsigned long long sv[6];
#pragma unroll
            for (int r = 0; r < 6; r++) sv[r] = packdup(sp[r]);
#pragma unroll
            for (int j = 0; j < 4; j++) {
                z2[0][j] = fma2(A0.x, sv[j],     z2[0][j]);
                z2[1][j] = fma2(A0.y, sv[j],     z2[1][j]);
                z2[0][j] = fma2(A1.x, sv[j + 1], z2[0][j]);
                z2[1][j] = fma2(A1.y, sv[j + 1], z2[1][j]);
                z2[0][j] = fma2(A2.x, sv[j + 2], z2[0][j]);
                z2[1][j] = fma2(A2.y, sv[j + 2], z2[1][j]);
            }
        }

        // unpack + relu
        float z[4][4];
#pragma unroll
        for (int ip = 0; ip < 2; ip++)
#pragma unroll
            for (int j = 0; j < 4; j++) {
                float2 u = unpack2(z2[ip][j]);
                z[2 * ip][j]     = fmaxf(u.x, 0.f);
                z[2 * ip + 1][j] = fmaxf(u.y, 0.f);
            }

        // ---- LayerNorm over 64 channels per t (reduce across 16 lanes sharing tn) ----
        float s1[4], s2[4];
#pragma unroll
        for (int j = 0; j < 4; j++) {
            s1[j] = z[0][j] + z[1][j] + z[2][j] + z[3][j];
            s2[j] = z[0][j]*z[0][j] + z[1][j]*z[1][j] + z[2][j]*z[2][j] + z[3][j]*z[3][j];
        }
#pragma unroll
        for (int off = 1; off < 16; off <<= 1) {
#pragma unroll
            for (int j = 0; j < 4; j++) {
                s1[j] += __shfl_xor_sync(0xffffffffu, s1[j], off);
                s2[j] += __shfl_xor_sync(0xffffffffu, s2[j], off);
            }
        }
        float mu[4], rs[4];
#pragma unroll
        for (int j = 0; j < 4; j++) {
            mu[j] = s1[j] * 0.015625f;
            float var = fmaf(-mu[j], mu[j], s2[j] * 0.015625f);
            rs[j] = rsqrtf(var + 1e-5f);
        }

        // ---- scale/shift + store out[b][n][o][t] ----
        float* op = out + (size_t)p * (CC * TT);
#pragma unroll
        for (int i = 0; i < 4; i++) {
            float g  = BIAS[128 + tm + i];
            float be = BIAS[192 + tm + i];
            float4 w;
            w.x = fmaf((z[i][0] - mu[0]) * rs[0], g, be);
            w.y = fmaf((z[i][1] - mu[1]) * rs[1], g, be);
            w.z = fmaf((z[i][2] - mu[2]) * rs[2], g, be);
            w.w = fmaf((z[i][3] - mu[3]) * rs[3], g, be);
            *reinterpret_cast<float4*>(op + (tm + i) * 16 + tn) = w;
        }
    }
}

// ---------------- launch ----------------
extern "C" void kernel_launch(void* const* d_in, const int* in_sizes, int n_in,
                              void* d_out, int out_size) {
    const float* x       = (const float*)d_in[0];
    const int*   edge    = (const int*)  d_in[1];
    const float* cheb_W  = (const float*)d_in[2];
    const float* cheb_b  = (const float*)d_in[3];
    const float* time_W  = (const float*)d_in[4];
    const float* time_b  = (const float*)d_in[5];
    const float* res_W   = (const float*)d_in[6];
    const float* res_b   = (const float*)d_in[7];
    const float* ln_g    = (const float*)d_in[8];
    const float* ln_b    = (const float*)d_in[9];
    float* out = (float*)d_out;

    const int* row = edge;
    const int* col = edge + EE;

    cudaFuncSetAttribute(fused_kernel, cudaFuncAttributeMaxDynamicSharedMemorySize, SMEM_BYTES);

    // CSR build
    zero_counts_kernel<<<(NN + 255) / 256, 256>>>();
    count_kernel<<<(EE + 255) / 256, 256>>>(row, col);
    dinv_kernel<<<(NN + 255) / 256, 256>>>();
    scan_kernel<<<1, 1024>>>();
    fill_kernel<<<(EE + 255) / 256, 256>>>(row, col);

    // Chebyshev propagations
    float* Tx1p; cudaGetSymbolAddress((void**)&Tx1p, d_Tx1);
    float* P2p;  cudaGetSymbolAddress((void**)&P2p,  d_P2);
    prop_kernel<<<NN, 256>>>(x, Tx1p);
    prop_kernel<<<NN, 256>>>(Tx1p, P2p);

    // Fused cheb-combine + temporal conv + residual + relu + LayerNorm
    fused_kernel<<<FUSED_GRID, 256, SMEM_BYTES>>>(
        x, cheb_W, cheb_b, time_W, time_b, res_W, res_b, ln_g, ln_b, out);
}

// round 5
// speedup vs baseline: 1.7041x; 1.5794x over previous
#include <cuda_runtime.h>
#include <cuda_fp16.h>
#include <mma.h>
#include <cstdint>
#include <cstddef>

using namespace nvcuda;

#define NN 10000
#define EE 160000
#define PAIRS 20000
#define NODE_FLOATS 512
#define NTILES 2500

// ---------------- device scratch ----------------
__device__ float d_Tx1[(size_t)PAIRS * NODE_FLOATS];
__device__ float d_P2 [(size_t)PAIRS * NODE_FLOATS];
__device__ int   d_degc[NN];
__device__ float d_dinv[NN];
__device__ int   d_cnt[NN];
__device__ int   d_ptr[NN + 1];
__device__ int   d_wr[NN];
__device__ int   d_csrc[EE];
__device__ float d_csw[EE];

// ---------------- CSR build ----------------
__global__ void zero_counts_kernel() {
    int i = blockIdx.x * blockDim.x + threadIdx.x;
    if (i < NN) { d_degc[i] = 0; d_cnt[i] = 0; }
}
__global__ void count_kernel(const int* __restrict__ row, const int* __restrict__ col) {
    int e = blockIdx.x * blockDim.x + threadIdx.x;
    if (e < EE) {
        atomicAdd(&d_degc[row[e]], 1);
        atomicAdd(&d_cnt[col[e]], 1);
    }
}
__global__ void dinv_kernel() {
    int i = blockIdx.x * blockDim.x + threadIdx.x;
    if (i < NN) {
        int d = d_degc[i];
        d_dinv[i] = (d > 0) ? rsqrtf((float)d) : 0.f;
    }
}
__global__ void scan_kernel() {
    __shared__ int wsum[32];
    __shared__ int carry;
    int tid = threadIdx.x, lane = tid & 31, wid = tid >> 5;
    if (tid == 0) carry = 0;
    __syncthreads();
    for (int base = 0; base < NN; base += 1024) {
        int i = base + tid;
        int v = (i < NN) ? d_cnt[i] : 0;
        int s = v;
#pragma unroll
        for (int off = 1; off < 32; off <<= 1) {
            int t = __shfl_up_sync(0xffffffffu, s, off);
            if (lane >= off) s += t;
        }
        if (lane == 31) wsum[wid] = s;
        __syncthreads();
        if (wid == 0) {
            int ws = wsum[lane];
#pragma unroll
            for (int off = 1; off < 32; off <<= 1) {
                int t = __shfl_up_sync(0xffffffffu, ws, off);
                if (lane >= off) ws += t;
            }
            wsum[lane] = ws;
        }
        __syncthreads();
        int incl = s + ((wid > 0) ? wsum[wid - 1] : 0);
        int c0 = carry;
        if (i < NN) { int ex = c0 + incl - v; d_ptr[i] = ex; d_wr[i] = ex; }
        __syncthreads();
        if (tid == 1023) carry = c0 + incl;
        __syncthreads();
    }
    if (threadIdx.x == 0) d_ptr[NN] = carry;
}
__global__ void fill_kernel(const int* __restrict__ row, const int* __restrict__ col) {
    int e = blockIdx.x * blockDim.x + threadIdx.x;
    if (e < EE) {
        int r = row[e], c = col[e];
        float wv = -(d_dinv[r] * d_dinv[c]);
        int pos = atomicAdd(&d_wr[c], 1);
        d_csrc[pos] = r;
        d_csw[pos]  = wv;
    }
}

// ---------------- propagation ----------------
__global__ __launch_bounds__(256) void prop_kernel(const float* __restrict__ z,
                                                   float* __restrict__ outp) {
    int n = blockIdx.x;
    int tid = threadIdx.x;
    int b = tid >> 7;
    int q = tid & 127;
    const float4* zb = reinterpret_cast<const float4*>(z) + (size_t)b * NN * 128;
    float4 acc = make_float4(0.f, 0.f, 0.f, 0.f);
    int s = d_ptr[n], e = d_ptr[n + 1];
    int k = s;
    for (; k + 1 < e; k += 2) {
        int u0 = d_csrc[k], u1 = d_csrc[k + 1];
        float w0 = d_csw[k], w1 = d_csw[k + 1];
        float4 v0 = zb[(size_t)u0 * 128 + q];
        float4 v1 = zb[(size_t)u1 * 128 + q];
        acc.x += w0 * v0.x + w1 * v1.x;
        acc.y += w0 * v0.y + w1 * v1.y;
        acc.z += w0 * v0.z + w1 * v1.z;
        acc.w += w0 * v0.w + w1 * v1.w;
    }
    if (k < e) {
        int u0 = d_csrc[k];
        float w0 = d_csw[k];
        float4 v0 = zb[(size_t)u0 * 128 + q];
        acc.x += w0 * v0.x; acc.y += w0 * v0.y;
        acc.z += w0 * v0.z; acc.w += w0 * v0.w;
    }
    reinterpret_cast<float4*>(outp)[(size_t)b * NN * 128 + (size_t)n * 128 + q] = acc;
}

// ================= persistent wmma dense kernel =================
// smem layout (bytes):
#define O_BIAS   0         // 256 floats = 1024
#define O_A1H    1024      // 128 x 104 halves = 26624   (alias: S_h 144x72, OUT fp32 32KB spans A1H+A1L)
#define O_A1L    27648     // 26624                       (alias: S_l)
#define O_B1H    54272     // 96 x 136 halves = 26112
#define O_B1L    80384     // 26112
#define O_B2H    106496    // 3 x 64 x 72 halves = 27648
#define O_B2L    134144    // 27648
#define O_RES    161792    // 128 x 68 floats = 34816
#define O_STG    196608    // 8 warps x 256 floats = 8192
#define TC_SMEM  204800

#define LDA1 104
#define LDB1 136
#define LDS2 72
#define LDB2 72
#define LDRES 68

__device__ __forceinline__ void split2(float a, float b, unsigned& uh, unsigned& ul) {
    __half h0 = __float2half_rn(a), h1 = __float2half_rn(b);
    __half l0 = __float2half_rn(a - __half2float(h0));
    __half l1 = __float2half_rn(b - __half2float(h1));
    __half2 H = __halves2half2(h0, h1), L = __halves2half2(l0, l1);
    uh = *reinterpret_cast<unsigned*>(&H);
    ul = *reinterpret_cast<unsigned*>(&L);
}

__global__ __launch_bounds__(256, 1) void tc_kernel(
    const float* __restrict__ x,
    const float* __restrict__ cheb_W, const float* __restrict__ cheb_b,
    const float* __restrict__ time_W, const float* __restrict__ time_b,
    const float* __restrict__ res_W,  const float* __restrict__ res_b,
    const float* __restrict__ ln_g,   const float* __restrict__ ln_b,
    float* __restrict__ outg)
{
    extern __shared__ char sm[];
    float* BIAS = reinterpret_cast<float*>(sm + O_BIAS);
    __half* A1h = reinterpret_cast<__half*>(sm + O_A1H);
    __half* A1l = reinterpret_cast<__half*>(sm + O_A1L);
    __half* B1h = reinterpret_cast<__half*>(sm + O_B1H);
    __half* B1l = reinterpret_cast<__half*>(sm + O_B1L);
    __half* B2h = reinterpret_cast<__half*>(sm + O_B2H);
    __half* B2l = reinterpret_cast<__half*>(sm + O_B2L);
    __half* Sh  = A1h;
    __half* Sl  = A1l;
    float* RES  = reinterpret_cast<float*>(sm + O_RES);
    float* STGb = reinterpret_cast<float*>(sm + O_STG);
    float* OUT  = reinterpret_cast<float*>(sm + O_A1H);

    int tid = threadIdx.x, warp = tid >> 5, lane = tid & 31;

    // ---- one-time weight staging ----
    // B1: rows k(96) x cols n(128): [cheb fold | res pad]
    for (int idx = tid; idx < 96 * 16; idx += 256) {
        int k = idx >> 4, n0 = (idx & 15) * 8;
        unsigned uh[4], ul[4];
#pragma unroll
        for (int i = 0; i < 4; i++) {
            float v[2];
#pragma unroll
            for (int j = 0; j < 2; j++) {
                int n = n0 + 2 * i + j;
                float val;
                if (n < 64) {
                    if (k < 32)      val = cheb_W[k * 64 + n] - cheb_W[4096 + k * 64 + n];
                    else if (k < 64) val = cheb_W[2048 + (k - 32) * 64 + n];
                    else             val = 2.f * cheb_W[4096 + (k - 64) * 64 + n];
                } else {
                    val = (k < 32) ? res_W[(n - 64) * 32 + k] : 0.f;
                }
                v[j] = val;
            }
            split2(v[0], v[1], uh[i], ul[i]);
        }
        *reinterpret_cast<uint4*>(&B1h[k * LDB1 + n0]) = make_uint4(uh[0], uh[1], uh[2], uh[3]);
        *reinterpret_cast<uint4*>(&B1l[k * LDB1 + n0]) = make_uint4(ul[0], ul[1], ul[2], ul[3]);
    }
    // B2[dt]: rows c(64) x cols o(64)
    for (int idx = tid; idx < 3 * 64 * 8; idx += 256) {
        int dt = idx / 512, rem = idx % 512;
        int c = rem >> 3, n0 = (rem & 7) * 8;
        unsigned uh[4], ul[4];
#pragma unroll
        for (int i = 0; i < 4; i++) {
            float v0 = time_W[(n0 + 2 * i) * 192 + c * 3 + dt];
            float v1 = time_W[(n0 + 2 * i + 1) * 192 + c * 3 + dt];
            split2(v0, v1, uh[i], ul[i]);
        }
        *reinterpret_cast<uint4*>(&B2h[dt * 4608 + c * LDB2 + n0]) = make_uint4(uh[0], uh[1], uh[2], uh[3]);
        *reinterpret_cast<uint4*>(&B2l[dt * 4608 + c * LDB2 + n0]) = make_uint4(ul[0], ul[1], ul[2], ul[3]);
    }
    if (tid < 64) {
        BIAS[tid]       = cheb_b[tid];
        BIAS[64 + tid]  = time_b[tid] + res_b[tid];
        BIAS[128 + tid] = ln_g[tid];
        BIAS[192 + tid] = ln_b[tid];
    }
    __syncthreads();

    float* stg = STGb + warp * 256;
    int er = lane >> 1, ec0 = (lane & 1) * 8;   // epilogue lane mapping

    for (int tile = blockIdx.x; tile < NTILES; tile += gridDim.x) {
        // ---- stage A1 = [x | Tx1 | P2], rows m = p*16 + t, f16 hi/lo ----
        {
            int m = tid >> 1, hf = tid & 1;
            int p = m >> 4, t = m & 15;
            size_t poff = (size_t)(tile * 8 + p) * NODE_FLOATS;
#pragma unroll
            for (int g = 0; g < 6; g++) {
                int k0 = hf * 48 + g * 8;
                const float* src = (k0 < 32) ? x + poff : (k0 < 64 ? d_Tx1 + poff : d_P2 + poff);
                int f0 = k0 & 31;
                unsigned uh[4], ul[4];
#pragma unroll
                for (int i = 0; i < 4; i++)
                    split2(src[(f0 + 2 * i) * 16 + t], src[(f0 + 2 * i + 1) * 16 + t], uh[i], ul[i]);
                *reinterpret_cast<uint4*>(&A1h[m * LDA1 + k0]) = make_uint4(uh[0], uh[1], uh[2], uh[3]);
                *reinterpret_cast<uint4*>(&A1l[m * LDA1 + k0]) = make_uint4(ul[0], ul[1], ul[2], ul[3]);
            }
        }
        __syncthreads();

        // ---- GEMM1: C1[128x128] = A[128x96] @ B1[96x128], 3 split terms ----
        wmma::fragment<wmma::accumulator, 16, 16, 16, float> acc[8];
#pragma unroll
        for (int nt = 0; nt < 8; nt++) wmma::fill_fragment(acc[nt], 0.f);
#pragma unroll
        for (int kt = 0; kt < 6; kt++) {
            wmma::fragment<wmma::matrix_a, 16, 16, 16, __half, wmma::row_major> ah, al;
            wmma::load_matrix_sync(ah, &A1h[(warp * 16) * LDA1 + kt * 16], LDA1);
            wmma::load_matrix_sync(al, &A1l[(warp * 16) * LDA1 + kt * 16], LDA1);
#pragma unroll
            for (int nt = 0; nt < 8; nt++) {
                wmma::fragment<wmma::matrix_b, 16, 16, 16, __half, wmma::row_major> bh, bl;
                wmma::load_matrix_sync(bh, &B1h[(kt * 16) * LDB1 + nt * 16], LDB1);
                wmma::load_matrix_sync(bl, &B1l[(kt * 16) * LDB1 + nt * 16], LDB1);
                wmma::mma_sync(acc[nt], ah, bh, acc[nt]);
                wmma::mma_sync(acc[nt], al, bh, acc[nt]);
                wmma::mma_sync(acc[nt], ah, bl, acc[nt]);
            }
        }
        __syncthreads();   // all A1 reads done; S may now overwrite A1 region

        // ---- zero S halo rows (t=-1 rows 0..7, t=16 rows 136..143) ----
        for (int i = tid; i < 288; i += 256) {
            int a = i / 144, r = i % 144;
            char* base = a ? reinterpret_cast<char*>(Sl) : reinterpret_cast<char*>(Sh);
            int off = (r < 72) ? r * 16 : 19584 + (r - 72) * 16;
            *reinterpret_cast<uint4*>(base + off) = make_uint4(0, 0, 0, 0);
        }

        // ---- epilogue 1: cols 0..63 -> s (relu+bias, split) at shifted rows; 64..127 -> RES ----
#pragma unroll
        for (int nt = 0; nt < 8; nt++) {
            wmma::store_matrix_sync(stg, acc[nt], 16, wmma::mem_row_major);
            __syncwarp();
            if (nt < 4) {
                int cc = nt * 16 + ec0;
                unsigned uh[4], ul[4];
#pragma unroll
                for (int i = 0; i < 4; i++) {
                    float v0 = fmaxf(stg[er * 16 + ec0 + 2 * i]     + BIAS[cc + 2 * i], 0.f);
                    float v1 = fmaxf(stg[er * 16 + ec0 + 2 * i + 1] + BIAS[cc + 2 * i + 1], 0.f);
                    split2(v0, v1, uh[i], ul[i]);
                }
                int sr = 8 * er + 8 + warp;
                *reinterpret_cast<uint4*>(&Sh[sr * LDS2 + cc]) = make_uint4(uh[0], uh[1], uh[2], uh[3]);
                *reinterpret_cast<uint4*>(&Sl[sr * LDS2 + cc]) = make_uint4(ul[0], ul[1], ul[2], ul[3]);
            } else {
                int cc = (nt - 4) * 16 + ec0;
                int mr = warp * 16 + er;
                float4 v0, v1;
                v0.x = stg[er * 16 + ec0 + 0] + BIAS[64 + cc + 0];
                v0.y = stg[er * 16 + ec0 + 1] + BIAS[64 + cc + 1];
                v0.z = stg[er * 16 + ec0 + 2] + BIAS[64 + cc + 2];
                v0.w = stg[er * 16 + ec0 + 3] + BIAS[64 + cc + 3];
                v1.x = stg[er * 16 + ec0 + 4] + BIAS[64 + cc + 4];
                v1.y = stg[er * 16 + ec0 + 5] + BIAS[64 + cc + 5];
                v1.z = stg[er * 16 + ec0 + 6] + BIAS[64 + cc + 6];
                v1.w = stg[er * 16 + ec0 + 7] + BIAS[64 + cc + 7];
                *reinterpret_cast<float4*>(&RES[mr * LDRES + cc])     = v0;
                *reinterpret_cast<float4*>(&RES[mr * LDRES + cc + 4]) = v1;
            }
            __syncwarp();
        }
        __syncthreads();

        // ---- GEMM2: temporal conv, 3 row-shifted GEMMs, 3 split terms ----
        wmma::fragment<wmma::accumulator, 16, 16, 16, float> acc2[4];
#pragma unroll
        for (int nt = 0; nt < 4; nt++) wmma::fill_fragment(acc2[nt], 0.f);
#pragma unroll
        for (int dt = 0; dt < 3; dt++) {
#pragma unroll
            for (int ct = 0; ct < 4; ct++) {
                wmma::fragment<wmma::matrix_a, 16, 16, 16, __half, wmma::row_major> ah, al;
                wmma::load_matrix_sync(ah, &Sh[(warp * 16 + dt * 8) * LDS2 + ct * 16], LDS2);
                wmma::load_matrix_sync(al, &Sl[(warp * 16 + dt * 8) * LDS2 + ct * 16], LDS2);
#pragma unroll
                for (int nt = 0; nt < 4; nt++) {
                    wmma::fragment<wmma::matrix_b, 16, 16, 16, __half, wmma::row_major> bh, bl;
                    wmma::load_matrix_sync(bh, &B2h[dt * 4608 + (ct * 16) * LDB2 + nt * 16], LDB2);
                    wmma::load_matrix_sync(bl, &B2l[dt * 4608 + (ct * 16) * LDB2 + nt * 16], LDB2);
                    wmma::mma_sync(acc2[nt], ah, bh, acc2[nt]);
                    wmma::mma_sync(acc2[nt], al, bh, acc2[nt]);
                    wmma::mma_sync(acc2[nt], ah, bl, acc2[nt]);
                }
            }
        }
        __syncthreads();   // S reads done (OUT will alias S later)

        // ---- epilogue 2: z = relu(D2 + RES) written back in place (m-order rows) ----
#pragma unroll
        for (int nt = 0; nt < 4; nt++) {
            wmma::store_matrix_sync(stg, acc2[nt], 16, wmma::mem_row_major);
            __syncwarp();
            int m2 = warp * 16 + er;
            int t2 = m2 >> 3, p2 = m2 & 7;
            int mr = p2 * 16 + t2;
            int cc = nt * 16 + ec0;
            float4 a = *reinterpret_cast<float4*>(&RES[mr * LDRES + cc]);
            float4 b = *reinterpret_cast<float4*>(&RES[mr * LDRES + cc + 4]);
            a.x = fmaxf(a.x + stg[er * 16 + ec0 + 0], 0.f);
            a.y = fmaxf(a.y + stg[er * 16 + ec0 + 1], 0.f);
            a.z = fmaxf(a.z + stg[er * 16 + ec0 + 2], 0.f);
            a.w = fmaxf(a.w + stg[er * 16 + ec0 + 3], 0.f);
            b.x = fmaxf(b.x + stg[er * 16 + ec0 + 4], 0.f);
            b.y = fmaxf(b.y + stg[er * 16 + ec0 + 5], 0.f);
            b.z = fmaxf(b.z + stg[er * 16 + ec0 + 6], 0.f);
            b.w = fmaxf(b.w + stg[er * 16 + ec0 + 7], 0.f);
            *reinterpret_cast<float4*>(&RES[mr * LDRES + cc])     = a;
            *reinterpret_cast<float4*>(&RES[mr * LDRES + cc + 4]) = b;
            __syncwarp();
        }
        __syncthreads();

        // ---- LayerNorm per (p,t) row (thread-local) -> OUT smem ----
        if (tid < 128) {
            int p = tid >> 4, t = tid & 15;
            float z[64];
            float s1 = 0.f, s2 = 0.f;
#pragma unroll
            for (int c = 0; c < 64; c++) {
                float v = RES[tid * LDRES + c];
                z[c] = v;
                s1 += v;
                s2 += v * v;
            }
            float mu = s1 * 0.015625f;
            float var = fmaf(-mu, mu, s2 * 0.015625f);
            float rs = rsqrtf(var + 1e-5f);
#pragma unroll
            for (int c = 0; c < 64; c++)
                OUT[p * 1024 + c * 16 + t] = fmaf((z[c] - mu) * rs, BIAS[128 + c], BIAS[192 + c]);
        }
        __syncthreads();

        // ---- coalesced global store: out[(tile*8+p)*1024 + c*16 + t] ----
        {
            float4* og = reinterpret_cast<float4*>(outg + (size_t)tile * 8192);
            const float4* o4 = reinterpret_cast<const float4*>(OUT);
            for (int i = tid; i < 2048; i += 256) og[i] = o4[i];
        }
        __syncthreads();
    }
}

// ---------------- launch ----------------
extern "C" void kernel_launch(void* const* d_in, const int* in_sizes, int n_in,
                              void* d_out, int out_size) {
    const float* x       = (const float*)d_in[0];
    const int*   edge    = (const int*)  d_in[1];
    const float* cheb_W  = (const float*)d_in[2];
    const float* cheb_b  = (const float*)d_in[3];
    const float* time_W  = (const float*)d_in[4];
    const float* time_b  = (const float*)d_in[5];
    const float* res_W   = (const float*)d_in[6];
    const float* res_b   = (const float*)d_in[7];
    const float* ln_g    = (const float*)d_in[8];
    const float* ln_b    = (const float*)d_in[9];
    float* out = (float*)d_out;

    const int* row = edge;
    const int* col = edge + EE;

    cudaFuncSetAttribute(tc_kernel, cudaFuncAttributeMaxDynamicSharedMemorySize, TC_SMEM);

    zero_counts_kernel<<<(NN + 255) / 256, 256>>>();
    count_kernel<<<(EE + 255) / 256, 256>>>(row, col);
    dinv_kernel<<<(NN + 255) / 256, 256>>>();
    scan_kernel<<<1, 1024>>>();
    fill_kernel<<<(EE + 255) / 256, 256>>>(row, col);

    float* Tx1p; cudaGetSymbolAddress((void**)&Tx1p, d_Tx1);
    float* P2p;  cudaGetSymbolAddress((void**)&P2p,  d_P2);
    prop_kernel<<<NN, 256>>>(x, Tx1p);
    prop_kernel<<<NN, 256>>>(Tx1p, P2p);

    tc_kernel<<<148, 256, TC_SMEM>>>(
        x, cheb_W, cheb_b, time_W, time_b, res_W, res_b, ln_g, ln_b, out);
}

// round 6
// speedup vs baseline: 1.8254x; 1.0712x over previous
#include <cuda_runtime.h>
#include <cuda_fp16.h>
#include <mma.h>
#include <cstdint>
#include <cstddef>

using namespace nvcuda;

#define NN 10000
#define EE 160000
#define PAIRS 20000
#define NODE_FLOATS 512
#define NTILES 2500

// ---------------- device scratch ----------------
__device__ float  d_Tx1[(size_t)PAIRS * NODE_FLOATS];
__device__ __half d_Tx1h[(size_t)PAIRS * NODE_FLOATS];
__device__ float  d_P2 [(size_t)PAIRS * NODE_FLOATS];
__device__ int   d_degc[NN];
__device__ float d_dinv[NN];
__device__ int   d_cnt[NN];
__device__ int   d_ptr[NN + 1];
__device__ int   d_wr[NN];
__device__ int   d_csrc[EE];
__device__ float d_csw[EE];

// ---------------- CSR build ----------------
__global__ void zero_counts_kernel() {
    int i = blockIdx.x * blockDim.x + threadIdx.x;
    if (i < NN) { d_degc[i] = 0; d_cnt[i] = 0; }
}
__global__ void count_kernel(const int* __restrict__ row, const int* __restrict__ col) {
    int e = blockIdx.x * blockDim.x + threadIdx.x;
    if (e < EE) {
        atomicAdd(&d_degc[row[e]], 1);
        atomicAdd(&d_cnt[col[e]], 1);
    }
}
// dinv + single-pass scan (1000 active threads x 10 elements)
__global__ void scan_kernel() {
    __shared__ int wsum[32];
    int tid = threadIdx.x, lane = tid & 31, wid = tid >> 5;
    for (int i = tid; i < NN; i += 1024) {
        int d = d_degc[i];
        d_dinv[i] = (d > 0) ? rsqrtf((float)d) : 0.f;
    }
    int loc[10];
    int s = 0;
    if (tid < 1000) {
        int base = tid * 10;
#pragma unroll
        for (int j = 0; j < 10; j++) { loc[j] = d_cnt[base + j]; s += loc[j]; }
    }
    int inc = s;
#pragma unroll
    for (int off = 1; off < 32; off <<= 1) {
        int t = __shfl_up_sync(0xffffffffu, inc, off);
        if (lane >= off) inc += t;
    }
    if (lane == 31) wsum[wid] = inc;
    __syncthreads();
    if (wid == 0) {
        int ws = wsum[lane];
#pragma unroll
        for (int off = 1; off < 32; off <<= 1) {
            int t = __shfl_up_sync(0xffffffffu, ws, off);
            if (lane >= off) ws += t;
        }
        wsum[lane] = ws;
    }
    __syncthreads();
    int excl = inc - s + ((wid > 0) ? wsum[wid - 1] : 0);
    if (tid < 1000) {
        int base = tid * 10;
        int run = excl;
#pragma unroll
        for (int j = 0; j < 10; j++) {
            d_ptr[base + j] = run;
            d_wr[base + j] = run;
            run += loc[j];
        }
    }
    if (tid == 0) d_ptr[NN] = wsum[31];
}
__global__ void fill_kernel(const int* __restrict__ row, const int* __restrict__ col) {
    int e = blockIdx.x * blockDim.x + threadIdx.x;
    if (e < EE) {
        int r = row[e], c = col[e];
        float wv = -(d_dinv[r] * d_dinv[c]);
        int pos = atomicAdd(&d_wr[c], 1);
        d_csrc[pos] = r;
        d_csw[pos]  = wv;
    }
}

// ---------------- prop1: fp32 gather of x; writes Tx1 fp32 + f16 copy ----------------
__global__ __launch_bounds__(256) void prop1_kernel(const float* __restrict__ z,
                                                    float* __restrict__ outp,
                                                    __half* __restrict__ outh) {
    int n = blockIdx.x;
    int tid = threadIdx.x;
    int b = tid >> 7;
    int q = tid & 127;
    const float4* zb = reinterpret_cast<const float4*>(z) + (size_t)b * NN * 128;
    float4 acc = make_float4(0.f, 0.f, 0.f, 0.f);
    int s = d_ptr[n], e = d_ptr[n + 1];
    int k = s;
    for (; k + 1 < e; k += 2) {
        int u0 = d_csrc[k], u1 = d_csrc[k + 1];
        float w0 = d_csw[k], w1 = d_csw[k + 1];
        float4 v0 = zb[(size_t)u0 * 128 + q];
        float4 v1 = zb[(size_t)u1 * 128 + q];
        acc.x += w0 * v0.x + w1 * v1.x;
        acc.y += w0 * v0.y + w1 * v1.y;
        acc.z += w0 * v0.z + w1 * v1.z;
        acc.w += w0 * v0.w + w1 * v1.w;
    }
    if (k < e) {
        int u0 = d_csrc[k];
        float w0 = d_csw[k];
        float4 v0 = zb[(size_t)u0 * 128 + q];
        acc.x += w0 * v0.x; acc.y += w0 * v0.y;
        acc.z += w0 * v0.z; acc.w += w0 * v0.w;
    }
    size_t o = (size_t)b * NN * 128 + (size_t)n * 128 + q;
    reinterpret_cast<float4*>(outp)[o] = acc;
    __half2 h0 = __floats2half2_rn(acc.x, acc.y);
    __half2 h1 = __floats2half2_rn(acc.z, acc.w);
    uint2 u;
    u.x = *reinterpret_cast<unsigned*>(&h0);
    u.y = *reinterpret_cast<unsigned*>(&h1);
    reinterpret_cast<uint2*>(outh)[o] = u;
}

// ---------------- prop2: f16 gather of Tx1h; fp32 accumulate; writes P2 fp32 ----------------
__global__ __launch_bounds__(256) void prop2_kernel(const __half* __restrict__ zh,
                                                    float* __restrict__ outp) {
    int n = blockIdx.x;
    int tid = threadIdx.x;
    int b = tid >> 7;
    int q = tid & 127;
    const uint2* zb = reinterpret_cast<const uint2*>(zh) + (size_t)b * NN * 128;
    float4 acc = make_float4(0.f, 0.f, 0.f, 0.f);
    int s = d_ptr[n], e = d_ptr[n + 1];
    int k = s;
    for (; k + 1 < e; k += 2) {
        int u0 = d_csrc[k], u1 = d_csrc[k + 1];
        float w0 = d_csw[k], w1 = d_csw[k + 1];
        uint2 r0 = zb[(size_t)u0 * 128 + q];
        uint2 r1 = zb[(size_t)u1 * 128 + q];
        float2 a0 = __half22float2(*reinterpret_cast<__half2*>(&r0.x));
        float2 a1 = __half22float2(*reinterpret_cast<__half2*>(&r0.y));
        float2 b0 = __half22float2(*reinterpret_cast<__half2*>(&r1.x));
        float2 b1 = __half22float2(*reinterpret_cast<__half2*>(&r1.y));
        acc.x += w0 * a0.x + w1 * b0.x;
        acc.y += w0 * a0.y + w1 * b0.y;
        acc.z += w0 * a1.x + w1 * b1.x;
        acc.w += w0 * a1.y + w1 * b1.y;
    }
    if (k < e) {
        int u0 = d_csrc[k];
        float w0 = d_csw[k];
        uint2 r0 = zb[(size_t)u0 * 128 + q];
        float2 a0 = __half22float2(*reinterpret_cast<__half2*>(&r0.x));
        float2 a1 = __half22float2(*reinterpret_cast<__half2*>(&r0.y));
        acc.x += w0 * a0.x; acc.y += w0 * a0.y;
        acc.z += w0 * a1.x; acc.w += w0 * a1.y;
    }
    reinterpret_cast<float4*>(outp)[(size_t)b * NN * 128 + (size_t)n * 128 + q] = acc;
}

// ================= persistent wmma dense kernel =================
#define O_BIAS   0         // 1024
#define O_A1H    1024      // 26624 (alias: S_h 144x72; OUT spans A1H+A1L)
#define O_A1L    27648     // 26624 (alias: S_l)
#define O_B1CH   54272     // 96x72 halves = 13824
#define O_B1CL   68096     // 13824
#define O_B1RH   81920     // 32x72 halves = 4608
#define O_B1RL   86528     // 4608
#define O_B2H    91136     // 3x64x72 halves = 27648
#define O_B2L    118784    // 27648
#define O_RES    146432    // 128x68 floats = 34816
#define O_STG    181248    // 8x256 floats = 8192
#define TC_SMEM  189440

#define LDA1 104
#define LDB1 72
#define LDS2 72
#define LDB2 72
#define LDRES 68

__device__ __forceinline__ void split2(float a, float b, unsigned& uh, unsigned& ul) {
    __half h0 = __float2half_rn(a), h1 = __float2half_rn(b);
    __half l0 = __float2half_rn(a - __half2float(h0));
    __half l1 = __float2half_rn(b - __half2float(h1));
    __half2 H = __halves2half2(h0, h1), L = __halves2half2(l0, l1);
    uh = *reinterpret_cast<unsigned*>(&H);
    ul = *reinterpret_cast<unsigned*>(&L);
}

__global__ __launch_bounds__(256, 1) void tc_kernel(
    const float* __restrict__ x,
    const float* __restrict__ cheb_W, const float* __restrict__ cheb_b,
    const float* __restrict__ time_W, const float* __restrict__ time_b,
    const float* __restrict__ res_W,  const float* __restrict__ res_b,
    const float* __restrict__ ln_g,   const float* __restrict__ ln_b,
    float* __restrict__ outg)
{
    extern __shared__ char sm[];
    float* BIAS  = reinterpret_cast<float*>(sm + O_BIAS);
    __half* A1h  = reinterpret_cast<__half*>(sm + O_A1H);
    __half* A1l  = reinterpret_cast<__half*>(sm + O_A1L);
    __half* B1ch = reinterpret_cast<__half*>(sm + O_B1CH);
    __half* B1cl = reinterpret_cast<__half*>(sm + O_B1CL);
    __half* B1rh = reinterpret_cast<__half*>(sm + O_B1RH);
    __half* B1rl = reinterpret_cast<__half*>(sm + O_B1RL);
    __half* B2h  = reinterpret_cast<__half*>(sm + O_B2H);
    __half* B2l  = reinterpret_cast<__half*>(sm + O_B2L);
    __half* Sh   = A1h;
    __half* Sl   = A1l;
    float* RES   = reinterpret_cast<float*>(sm + O_RES);
    float* STGb  = reinterpret_cast<float*>(sm + O_STG);
    float* OUT   = reinterpret_cast<float*>(sm + O_A1H);

    int tid = threadIdx.x, warp = tid >> 5, lane = tid & 31;

    // ---- one-time weight staging ----
    // B1c: rows k(96) x cols n(64): cheb fold
    for (int idx = tid; idx < 96 * 8; idx += 256) {
        int k = idx >> 3, n0 = (idx & 7) * 8;
        unsigned uh[4], ul[4];
#pragma unroll
        for (int i = 0; i < 4; i++) {
            float v[2];
#pragma unroll
            for (int j = 0; j < 2; j++) {
                int n = n0 + 2 * i + j;
                float val;
                if (k < 32)      val = cheb_W[k * 64 + n] - cheb_W[4096 + k * 64 + n];
                else if (k < 64) val = cheb_W[2048 + (k - 32) * 64 + n];
                else             val = 2.f * cheb_W[4096 + (k - 64) * 64 + n];
                v[j] = val;
            }
            split2(v[0], v[1], uh[i], ul[i]);
        }
        *reinterpret_cast<uint4*>(&B1ch[k * LDB1 + n0]) = make_uint4(uh[0], uh[1], uh[2], uh[3]);
        *reinterpret_cast<uint4*>(&B1cl[k * LDB1 + n0]) = make_uint4(ul[0], ul[1], ul[2], ul[3]);
    }
    // B1r: rows k(32) x cols n(64): res weights
    for (int idx = tid; idx < 32 * 8; idx += 256) {
        int k = idx >> 3, n0 = (idx & 7) * 8;
        unsigned uh[4], ul[4];
#pragma unroll
        for (int i = 0; i < 4; i++) {
            float v0 = res_W[(n0 + 2 * i) * 32 + k];
            float v1 = res_W[(n0 + 2 * i + 1) * 32 + k];
            split2(v0, v1, uh[i], ul[i]);
        }
        *reinterpret_cast<uint4*>(&B1rh[k * LDB1 + n0]) = make_uint4(uh[0], uh[1], uh[2], uh[3]);
        *reinterpret_cast<uint4*>(&B1rl[k * LDB1 + n0]) = make_uint4(ul[0], ul[1], ul[2], ul[3]);
    }
    // B2[dt]: rows c(64) x cols o(64)
    for (int idx = tid; idx < 3 * 64 * 8; idx += 256) {
        int dt = idx / 512, rem = idx % 512;
        int c = rem >> 3, n0 = (rem & 7) * 8;
        unsigned uh[4], ul[4];
#pragma unroll
        for (int i = 0; i < 4; i++) {
            float v0 = time_W[(n0 + 2 * i) * 192 + c * 3 + dt];
            float v1 = time_W[(n0 + 2 * i + 1) * 192 + c * 3 + dt];
            split2(v0, v1, uh[i], ul[i]);
        }
        *reinterpret_cast<uint4*>(&B2h[dt * 4608 + c * LDB2 + n0]) = make_uint4(uh[0], uh[1], uh[2], uh[3]);
        *reinterpret_cast<uint4*>(&B2l[dt * 4608 + c * LDB2 + n0]) = make_uint4(ul[0], ul[1], ul[2], ul[3]);
    }
    if (tid < 64) {
        BIAS[tid]       = cheb_b[tid];
        BIAS[64 + tid]  = time_b[tid] + res_b[tid];
        BIAS[128 + tid] = ln_g[tid];
        BIAS[192 + tid] = ln_b[tid];
    }
    __syncthreads();

    float* stg = STGb + warp * 256;
    int er = lane >> 1, ec0 = (lane & 1) * 8;

    for (int tile = blockIdx.x; tile < NTILES; tile += gridDim.x) {
        // ---- stage A1 = [x | Tx1 | P2], rows m = p*16 + t, f16 hi/lo ----
        {
            int m = tid >> 1, hf = tid & 1;
            int p = m >> 4, t = m & 15;
            size_t poff = (size_t)(tile * 8 + p) * NODE_FLOATS;
#pragma unroll
            for (int g = 0; g < 6; g++) {
                int k0 = hf * 48 + g * 8;
                const float* src = (k0 < 32) ? x + poff : (k0 < 64 ? d_Tx1 + poff : d_P2 + poff);
                int f0 = k0 & 31;
                unsigned uh[4], ul[4];
#pragma unroll
                for (int i = 0; i < 4; i++)
                    split2(src[(f0 + 2 * i) * 16 + t], src[(f0 + 2 * i + 1) * 16 + t], uh[i], ul[i]);
                *reinterpret_cast<uint4*>(&A1h[m * LDA1 + k0]) = make_uint4(uh[0], uh[1], uh[2], uh[3]);
                *reinterpret_cast<uint4*>(&A1l[m * LDA1 + k0]) = make_uint4(ul[0], ul[1], ul[2], ul[3]);
            }
        }
        __syncthreads();

        // ---- GEMM1a: cheb C[128x64] = A[:, 0:96] @ B1c ----
        wmma::fragment<wmma::accumulator, 16, 16, 16, float> accc[4], accr[4];
#pragma unroll
        for (int nt = 0; nt < 4; nt++) { wmma::fill_fragment(accc[nt], 0.f); wmma::fill_fragment(accr[nt], 0.f); }
#pragma unroll
        for (int kt = 0; kt < 6; kt++) {
            wmma::fragment<wmma::matrix_a, 16, 16, 16, __half, wmma::row_major> ah, al;
            wmma::load_matrix_sync(ah, &A1h[(warp * 16) * LDA1 + kt * 16], LDA1);
            wmma::load_matrix_sync(al, &A1l[(warp * 16) * LDA1 + kt * 16], LDA1);
#pragma unroll
            for (int nt = 0; nt < 4; nt++) {
                wmma::fragment<wmma::matrix_b, 16, 16, 16, __half, wmma::row_major> bh, bl;
                wmma::load_matrix_sync(bh, &B1ch[(kt * 16) * LDB1 + nt * 16], LDB1);
                wmma::load_matrix_sync(bl, &B1cl[(kt * 16) * LDB1 + nt * 16], LDB1);
                wmma::mma_sync(accc[nt], ah, bh, accc[nt]);
                wmma::mma_sync(accc[nt], al, bh, accc[nt]);
                wmma::mma_sync(accc[nt], ah, bl, accc[nt]);
            }
            // ---- GEMM1b: res, K=32 only ----
            if (kt < 2) {
#pragma unroll
                for (int nt = 0; nt < 4; nt++) {
                    wmma::fragment<wmma::matrix_b, 16, 16, 16, __half, wmma::row_major> bh, bl;
                    wmma::load_matrix_sync(bh, &B1rh[(kt * 16) * LDB1 + nt * 16], LDB1);
                    wmma::load_matrix_sync(bl, &B1rl[(kt * 16) * LDB1 + nt * 16], LDB1);
                    wmma::mma_sync(accr[nt], ah, bh, accr[nt]);
                    wmma::mma_sync(accr[nt], al, bh, accr[nt]);
                    wmma::mma_sync(accr[nt], ah, bl, accr[nt]);
                }
            }
        }
        __syncthreads();   // all A1 reads done; S may overwrite A1 region

        // ---- zero S halo rows ----
        for (int i = tid; i < 288; i += 256) {
            int a = i / 144, r = i % 144;
            char* base = a ? reinterpret_cast<char*>(Sl) : reinterpret_cast<char*>(Sh);
            int off = (r < 72) ? r * 16 : 19584 + (r - 72) * 16;
            *reinterpret_cast<uint4*>(base + off) = make_uint4(0, 0, 0, 0);
        }

        // ---- epilogue 1: cheb -> s (relu+bias, split, shifted rows); res -> RES ----
#pragma unroll
        for (int nt = 0; nt < 4; nt++) {
            wmma::store_matrix_sync(stg, accc[nt], 16, wmma::mem_row_major);
            __syncwarp();
            int cc = nt * 16 + ec0;
            unsigned uh[4], ul[4];
#pragma unroll
            for (int i = 0; i < 4; i++) {
                float v0 = fmaxf(stg[er * 16 + ec0 + 2 * i]     + BIAS[cc + 2 * i], 0.f);
                float v1 = fmaxf(stg[er * 16 + ec0 + 2 * i + 1] + BIAS[cc + 2 * i + 1], 0.f);
                split2(v0, v1, uh[i], ul[i]);
            }
            int sr = 8 * er + 8 + warp;
            *reinterpret_cast<uint4*>(&Sh[sr * LDS2 + cc]) = make_uint4(uh[0], uh[1], uh[2], uh[3]);
            *reinterpret_cast<uint4*>(&Sl[sr * LDS2 + cc]) = make_uint4(ul[0], ul[1], ul[2], ul[3]);
            __syncwarp();
        }
#pragma unroll
        for (int nt = 0; nt < 4; nt++) {
            wmma::store_matrix_sync(stg, accr[nt], 16, wmma::mem_row_major);
            __syncwarp();
            int cc = nt * 16 + ec0;
            int mr = warp * 16 + er;
            float4 v0, v1;
            v0.x = stg[er * 16 + ec0 + 0] + BIAS[64 + cc + 0];
            v0.y = stg[er * 16 + ec0 + 1] + BIAS[64 + cc + 1];
            v0.z = stg[er * 16 + ec0 + 2] + BIAS[64 + cc + 2];
            v0.w = stg[er * 16 + ec0 + 3] + BIAS[64 + cc + 3];
            v1.x = stg[er * 16 + ec0 + 4] + BIAS[64 + cc + 4];
            v1.y = stg[er * 16 + ec0 + 5] + BIAS[64 + cc + 5];
            v1.z = stg[er * 16 + ec0 + 6] + BIAS[64 + cc + 6];
            v1.w = stg[er * 16 + ec0 + 7] + BIAS[64 + cc + 7];
            *reinterpret_cast<float4*>(&RES[mr * LDRES + cc])     = v0;
            *reinterpret_cast<float4*>(&RES[mr * LDRES + cc + 4]) = v1;
            __syncwarp();
        }
        __syncthreads();

        // ---- GEMM2: temporal conv, 3 row-shifted GEMMs, 3 split terms ----
        wmma::fragment<wmma::accumulator, 16, 16, 16, float> acc2[4];
#pragma unroll
        for (int nt = 0; nt < 4; nt++) wmma::fill_fragment(acc2[nt], 0.f);
#pragma unroll
        for (int dt = 0; dt < 3; dt++) {
#pragma unroll
            for (int ct = 0; ct < 4; ct++) {
                wmma::fragment<wmma::matrix_a, 16, 16, 16, __half, wmma::row_major> ah, al;
                wmma::load_matrix_sync(ah, &Sh[(warp * 16 + dt * 8) * LDS2 + ct * 16], LDS2);
                wmma::load_matrix_sync(al, &Sl[(warp * 16 + dt * 8) * LDS2 + ct * 16], LDS2);
#pragma unroll
                for (int nt = 0; nt < 4; nt++) {
                    wmma::fragment<wmma::matrix_b, 16, 16, 16, __half, wmma::row_major> bh, bl;
                    wmma::load_matrix_sync(bh, &B2h[dt * 4608 + (ct * 16) * LDB2 + nt * 16], LDB2);
                    wmma::load_matrix_sync(bl, &B2l[dt * 4608 + (ct * 16) * LDB2 + nt * 16], LDB2);
                    wmma::mma_sync(acc2[nt], ah, bh, acc2[nt]);
                    wmma::mma_sync(acc2[nt], al, bh, acc2[nt]);
                    wmma::mma_sync(acc2[nt], ah, bl, acc2[nt]);
                }
            }
        }
        __syncthreads();

        // ---- epilogue 2: z = relu(D2 + RES) in place ----
#pragma unroll
        for (int nt = 0; nt < 4; nt++) {
            wmma::store_matrix_sync(stg, acc2[nt], 16, wmma::mem_row_major);
            __syncwarp();
            int m2 = warp * 16 + er;
            int t2 = m2 >> 3, p2 = m2 & 7;
            int mr = p2 * 16 + t2;
            int cc = nt * 16 + ec0;
            float4 a = *reinterpret_cast<float4*>(&RES[mr * LDRES + cc]);
            float4 b = *reinterpret_cast<float4*>(&RES[mr * LDRES + cc + 4]);
            a.x = fmaxf(a.x + stg[er * 16 + ec0 + 0], 0.f);
            a.y = fmaxf(a.y + stg[er * 16 + ec0 + 1], 0.f);
            a.z = fmaxf(a.z + stg[er * 16 + ec0 + 2], 0.f);
            a.w = fmaxf(a.w + stg[er * 16 + ec0 + 3], 0.f);
            b.x = fmaxf(b.x + stg[er * 16 + ec0 + 4], 0.f);
            b.y = fmaxf(b.y + stg[er * 16 + ec0 + 5], 0.f);
            b.z = fmaxf(b.z + stg[er * 16 + ec0 + 6], 0.f);
            b.w = fmaxf(b.w + stg[er * 16 + ec0 + 7], 0.f);
            *reinterpret_cast<float4*>(&RES[mr * LDRES + cc])     = a;
            *reinterpret_cast<float4*>(&RES[mr * LDRES + cc + 4]) = b;
            __syncwarp();
        }
        __syncthreads();

        // ---- LayerNorm per (p,t) row -> OUT smem ----
        if (tid < 128) {
            int p = tid >> 4, t = tid & 15;
            float z[64];
            float s1 = 0.f, s2 = 0.f;
#pragma unroll
            for (int c = 0; c < 64; c++) {
                float v = RES[tid * LDRES + c];
                z[c] = v;
                s1 += v;
                s2 += v * v;
            }
            float mu = s1 * 0.015625f;
            float var = fmaf(-mu, mu, s2 * 0.015625f);
            float rs = rsqrtf(var + 1e-5f);
#pragma unroll
            for (int c = 0; c < 64; c++)
                OUT[p * 1024 + c * 16 + t] = fmaf((z[c] - mu) * rs, BIAS[128 + c], BIAS[192 + c]);
        }
        __syncthreads();

        // ---- coalesced global store ----
        {
            float4* og = reinterpret_cast<float4*>(outg + (size_t)tile * 8192);
            const float4* o4 = reinterpret_cast<const float4*>(OUT);
            for (int i = tid; i < 2048; i += 256) og[i] = o4[i];
        }
        __syncthreads();
    }
}

// ---------------- launch ----------------
extern "C" void kernel_launch(void* const* d_in, const int* in_sizes, int n_in,
                              void* d_out, int out_size) {
    const float* x       = (const float*)d_in[0];
    const int*   edge    = (const int*)  d_in[1];
    const float* cheb_W  = (const float*)d_in[2];
    const float* cheb_b  = (const float*)d_in[3];
    const float* time_W  = (const float*)d_in[4];
    const float* time_b  = (const float*)d_in[5];
    const float* res_W   = (const float*)d_in[6];
    const float* res_b   = (const float*)d_in[7];
    const float* ln_g    = (const float*)d_in[8];
    const float* ln_b    = (const float*)d_in[9];
    float* out = (float*)d_out;

    const int* row = edge;
    const int* col = edge + EE;

    cudaFuncSetAttribute(tc_kernel, cudaFuncAttributeMaxDynamicSharedMemorySize, TC_SMEM);

    zero_counts_kernel<<<(NN + 255) / 256, 256>>>();
    count_kernel<<<(EE + 255) / 256, 256>>>(row, col);
    scan_kernel<<<1, 1024>>>();
    fill_kernel<<<(EE + 255) / 256, 256>>>(row, col);

    float*  Tx1p;  cudaGetSymbolAddress((void**)&Tx1p,  d_Tx1);
    __half* Tx1hp; cudaGetSymbolAddress((void**)&Tx1hp, d_Tx1h);
    float*  P2p;   cudaGetSymbolAddress((void**)&P2p,   d_P2);
    prop1_kernel<<<NN, 256>>>(x, Tx1p, Tx1hp);
    prop2_kernel<<<NN, 256>>>(Tx1hp, P2p);

    tc_kernel<<<148, 256, TC_SMEM>>>(
        x, cheb_W, cheb_b, time_W, time_b, res_W, res_b, ln_g, ln_b, out);
}